// round 12
// baseline (speedup 1.0000x reference)
#include <cuda_runtime.h>
#include <cuda_bf16.h>
#include <math.h>
#include <stdint.h>

#define NN   100000
#define EE   1600000
#define FIN  700
#define K0P  704
#define HH   128
#define EPSV 1e-5f

// ---------------- scratch (static device globals; zero-init, no runtime alloc) ----
__device__ float g_h  [(size_t)NN * HH];
__device__ float g_hc [(size_t)NN * 256];        // [self(128) | neigh(128)] per row
__device__ float g_z  [(size_t)NN * 128];        // head pre-activations (stride 128)
__device__ float g_denom[NN];
__device__ int   g_deg[NN];
__device__ int   g_rowptr[NN + 1];
__device__ int   g_colidx[EE];
__device__ int   g_bsums[128];
__device__ __align__(16) float g_stats[256];
__device__ __align__(16) float g_ab[256];

// bf16 split weights (A operands are split in-GEMM)
__device__ __nv_bfloat16 g_B0h[256 * K0P];
__device__ __nv_bfloat16 g_B0l[256 * K0P];
__device__ __nv_bfloat16 g_BLh[3 * 256 * HH];
__device__ __nv_bfloat16 g_BLl[3 * 256 * HH];
__device__ __nv_bfloat16 g_BHh[128 * HH];        // head W1 padded to 128 cols
__device__ __nv_bfloat16 g_BHl[128 * HH];

// ---------------- helpers ------------------------------------------------------
__device__ __forceinline__ void split_bf16(float x, __nv_bfloat16& h, __nv_bfloat16& l) {
    h = __float2bfloat16(x);
    l = __float2bfloat16(x - __bfloat162float(h));
}
__device__ __forceinline__ uint32_t pkbf2(__nv_bfloat16 a, __nv_bfloat16 b) {
    __nv_bfloat162 t = __halves2bfloat162(a, b);
    return *reinterpret_cast<uint32_t*>(&t);
}
__device__ __forceinline__ void cp16(uint32_t s, const void* g) {
    asm volatile("cp.async.cg.shared.global [%0], [%1], 16;" :: "r"(s), "l"(g));
}
__device__ __forceinline__ void ldsm4(uint32_t& r0, uint32_t& r1, uint32_t& r2, uint32_t& r3, uint32_t a) {
    asm volatile("ldmatrix.sync.aligned.m8n8.x4.shared.b16 {%0,%1,%2,%3}, [%4];"
                 : "=r"(r0), "=r"(r1), "=r"(r2), "=r"(r3) : "r"(a));
}
__device__ __forceinline__ void mma16816(float* c, const uint32_t* a, const uint32_t* b) {
    asm volatile("mma.sync.aligned.m16n8k16.row.col.f32.bf16.bf16.f32 "
                 "{%0,%1,%2,%3}, {%4,%5,%6,%7}, {%8,%9}, {%0,%1,%2,%3};"
                 : "+f"(c[0]), "+f"(c[1]), "+f"(c[2]), "+f"(c[3])
                 : "r"(a[0]), "r"(a[1]), "r"(a[2]), "r"(a[3]), "r"(b[0]), "r"(b[1]));
}

// ---------------- CSR construction --------------------------------------------
__global__ void k_zero_deg() {
    int i = blockIdx.x * blockDim.x + threadIdx.x;
    if (i < NN) g_deg[i] = 0;
}
__global__ void k_count(const int* __restrict__ graph) {
    int e = blockIdx.x * blockDim.x + threadIdx.x;
    if (e < EE) atomicAdd(&g_deg[graph[2 * e + 1]], 1);
}
__global__ void k_scan1() {
    __shared__ int s[1024];
    int tid = threadIdx.x;
    int i = blockIdx.x * 1024 + tid;
    int v = (i < NN) ? g_deg[i] : 0;
    s[tid] = v;
    __syncthreads();
    #pragma unroll
    for (int off = 1; off < 1024; off <<= 1) {
        int t = (tid >= off) ? s[tid - off] : 0;
        __syncthreads();
        s[tid] += t;
        __syncthreads();
    }
    if (i < NN) g_rowptr[i + 1] = s[tid];
    if (tid == 1023) g_bsums[blockIdx.x] = s[1023];
}
__global__ void k_scan2() {
    if (threadIdx.x == 0) {
        const int nb = (NN + 1023) / 1024;
        int acc = 0;
        for (int i = 0; i < nb; i++) { int t = g_bsums[i]; g_bsums[i] = acc; acc += t; }
    }
}
__global__ void k_scan3() {
    int i = blockIdx.x * blockDim.x + threadIdx.x;
    if (i >= NN) return;
    g_rowptr[i + 1] += g_bsums[i >> 10];
    if (i == 0) g_rowptr[0] = 0;
    int d = g_deg[i];
    g_denom[i] = (float)((d > 1) ? d : 1);
    g_deg[i] = 0;
}
__global__ void k_fill(const int* __restrict__ graph) {
    int e = blockIdx.x * blockDim.x + threadIdx.x;
    if (e >= EE) return;
    int src = graph[2 * e + 0];
    int dst = graph[2 * e + 1];
    int pos = g_rowptr[dst] + atomicAdd(&g_deg[dst], 1);
    g_colidx[pos] = src;
}

// ---------------- weight conversion --------------------------------------------
__global__ void k_convW0(const float* __restrict__ Ws, const float* __restrict__ Wn) {
    int idx = blockIdx.x * blockDim.x + threadIdx.x;
    if (idx >= 256 * K0P) return;
    int n = idx / K0P, k = idx % K0P;
    float v = 0.f;
    if (k < FIN) v = (n < HH) ? Ws[(size_t)k * HH + n] : Wn[(size_t)k * HH + (n - HH)];
    split_bf16(v, g_B0h[idx], g_B0l[idx]);
}
__global__ void k_convWL(const float* __restrict__ Ws, const float* __restrict__ Wn) {
    int idx = blockIdx.x * blockDim.x + threadIdx.x;
    if (idx >= 3 * 256 * HH) return;
    int l = idx / (256 * HH);
    int rem = idx % (256 * HH);
    int n = rem / HH, k = rem % HH;
    float v = (n < HH) ? Ws[(size_t)l * HH * HH + k * HH + n]
                       : Wn[(size_t)l * HH * HH + k * HH + (n - HH)];
    split_bf16(v, g_BLh[idx], g_BLl[idx]);
}
__global__ void k_convW1(const float* __restrict__ W1) {
    int idx = blockIdx.x * blockDim.x + threadIdx.x;
    if (idx >= 128 * HH) return;
    int n = idx / HH, k = idx % HH;
    float v = (n < 64) ? W1[(size_t)k * 64 + n] : 0.f;
    split_bf16(v, g_BHh[idx], g_BHl[idx]);
}

// ---------------- split-precision tensor GEMM, fp32 A fed in-kernel ------------
// R6 geometry (BM=128, BN=128, BK=16, 2-stage, static 48KB smem), but with a
// SINGLE __syncthreads per iteration: after wait+sync at the top of iter kt,
// stage (kt+1)&1 is provably idle (its readers finished iter kt-1 before the
// barrier), so stsA(kt+1)/cpB(kt+1) write it immediately; racing warps block at
// their own next-iteration barrier before touching stage kt.
#define TILE_B 6144
#define STAGE_B 24576
__global__ void __launch_bounds__(256) gemm_split(
    const float* __restrict__ A, int K, int Kpad,
    const __nv_bfloat16* __restrict__ Bh0, const __nv_bfloat16* __restrict__ Bl0,
    float* __restrict__ C, int M, int NCs)
{
    __shared__ __align__(16) char smem[49152];
    const uint32_t sb = (uint32_t)__cvta_generic_to_shared(smem);
    const int tid = threadIdx.x;
    const int bx = blockIdx.x, by = blockIdx.y;
    const int row0 = by * 128;
    const __nv_bfloat16* Bh = Bh0 + (size_t)bx * 128 * Kpad;
    const __nv_bfloat16* Bl = Bl0 + (size_t)bx * 128 * Kpad;
    const int KT = Kpad >> 4;

    const int ar = tid >> 1, aq = tid & 1;
    const int agr = row0 + ar;
    const float* Arow = A + (size_t)agr * K;

    float4 hv0, hv1;   // A tile (kt+1) held in regs
    float4 nv0, nv1;   // A tile (kt+2) loading

    auto ldgA = [&](int kt, float4& v0, float4& v1) {
        v0 = make_float4(0.f, 0.f, 0.f, 0.f);
        v1 = v0;
        int kb = kt * 16 + aq * 8;
        if (agr < M) {
            if (kb + 3 < K) v0 = *reinterpret_cast<const float4*>(Arow + kb);
            if (kb + 7 < K) v1 = *reinterpret_cast<const float4*>(Arow + kb + 4);
        }
    };
    auto stsA = [&](int stage, float4 v0, float4 v1) {
        float f[8] = {v0.x, v0.y, v0.z, v0.w, v1.x, v1.y, v1.z, v1.w};
        __nv_bfloat16 hh[8], ll[8];
        #pragma unroll
        for (int i = 0; i < 8; i++) split_bf16(f[i], hh[i], ll[i]);
        uint4 hvv, lvv;
        hvv.x = pkbf2(hh[0], hh[1]); hvv.y = pkbf2(hh[2], hh[3]);
        hvv.z = pkbf2(hh[4], hh[5]); hvv.w = pkbf2(hh[6], hh[7]);
        lvv.x = pkbf2(ll[0], ll[1]); lvv.y = pkbf2(ll[2], ll[3]);
        lvv.z = pkbf2(ll[4], ll[5]); lvv.w = pkbf2(ll[6], ll[7]);
        char* dst = smem + stage * STAGE_B + ar * 48 + aq * 16;
        *reinterpret_cast<uint4*>(dst) = hvv;
        *reinterpret_cast<uint4*>(dst + TILE_B) = lvv;
    };
    auto cpB = [&](int kt) {
        uint32_t base = sb + (uint32_t)(kt & 1) * STAGE_B + 2u * TILE_B;
        int r = tid >> 1, q = tid & 1;
        uint32_t so = base + (uint32_t)(r * 48 + q * 16);
        size_t gb = (size_t)r * Kpad + kt * 16 + q * 8;
        cp16(so, Bh + gb);
        cp16(so + TILE_B, Bl + gb);
        asm volatile("cp.async.commit_group;");
    };

    // prologue: stage 0 fully prepared; A(1) held in regs. cpB(1) is issued
    // inside iter 0 (single outstanding cp group at any time).
    {
        float4 a0, a1;
        ldgA(0, a0, a1);
        ldgA(1, hv0, hv1);
        cpB(0);
        stsA(0, a0, a1);
    }

    const int lane = tid & 31, w = tid >> 5;
    const int wm = w >> 2, wn = w & 3;
    const int lr = lane >> 2, lc = lane & 3;
    const int mat = lane >> 3, r8 = lane & 7;

    float acc[4][4][4];
    #pragma unroll
    for (int a = 0; a < 4; a++)
        #pragma unroll
        for (int b = 0; b < 4; b++)
            #pragma unroll
            for (int d = 0; d < 4; d++) acc[a][b][d] = 0.f;

    for (int kt = 0; kt < KT; ++kt) {
        asm volatile("cp.async.wait_group 0;");   // cpB(kt) complete
        __syncthreads();                           // all iter kt-1 reads done

        // stage (kt+1)&1 is now idle: feed it for the next iteration
        if (kt + 1 < KT) {
            stsA((kt + 1) & 1, hv0, hv1);
            cpB(kt + 1);
        }
        if (kt + 2 < KT) ldgA(kt + 2, nv0, nv1);

        uint32_t base = sb + (uint32_t)(kt & 1) * STAGE_B;

        uint32_t bh[2][4], bl[2][4];
        #pragma unroll
        for (int p = 0; p < 2; p++) {
            int brow = wn * 32 + p * 16 + r8 + (mat >> 1) * 8;
            uint32_t addr = base + 2u * TILE_B + (uint32_t)(brow * 48 + ((mat & 1) * 8) * 2);
            ldsm4(bh[p][0], bh[p][1], bh[p][2], bh[p][3], addr);
            ldsm4(bl[p][0], bl[p][1], bl[p][2], bl[p][3], addr + TILE_B);
        }
        #pragma unroll
        for (int mf = 0; mf < 4; ++mf) {
            int arow = wm * 64 + mf * 16 + r8 + (mat & 1) * 8;
            uint32_t aaddr = base + (uint32_t)(arow * 48 + ((mat >> 1) * 8) * 2);
            uint32_t ahr[4], alr[4];
            ldsm4(ahr[0], ahr[1], ahr[2], ahr[3], aaddr);
            ldsm4(alr[0], alr[1], alr[2], alr[3], aaddr + TILE_B);
            #pragma unroll
            for (int nf = 0; nf < 4; ++nf) {
                const uint32_t* bhp = &bh[nf >> 1][(nf & 1) * 2];
                const uint32_t* blp = &bl[nf >> 1][(nf & 1) * 2];
                mma16816(acc[mf][nf], ahr, bhp);
                mma16816(acc[mf][nf], alr, bhp);
                mma16816(acc[mf][nf], ahr, blp);
            }
        }
        if (kt + 2 < KT) { hv0 = nv0; hv1 = nv1; }
    }

    #pragma unroll
    for (int mf = 0; mf < 4; ++mf) {
        #pragma unroll
        for (int nf = 0; nf < 4; ++nf) {
            int r = row0 + wm * 64 + mf * 16 + lr;
            int cc = bx * 128 + wn * 32 + nf * 8 + lc * 2;
            if (r < M)
                *reinterpret_cast<float2*>(C + (size_t)r * NCs + cc) =
                    make_float2(acc[mf][nf][0], acc[mf][nf][1]);
            if (r + 8 < M)
                *reinterpret_cast<float2*>(C + (size_t)(r + 8) * NCs + cc) =
                    make_float2(acc[mf][nf][2], acc[mf][nf][3]);
        }
    }
}

// ---------------- fused CSR gather + bias + BN stats (warp-per-node) -----------
#define AGG_NPW 16
__global__ void __launch_bounds__(256) k_aggcomb(float* __restrict__ hc,
                                                 const float* __restrict__ bias) {
    __shared__ float sst[256];
    const int tid = threadIdx.x;
    const int lane = tid & 31;
    const int gw = blockIdx.x * 8 + (tid >> 5);
    const int c4 = lane * 4;
    const int n0 = gw * AGG_NPW;
    if (tid < 256) sst[tid] = 0.f;
    __syncthreads();

    if (n0 < NN) {
        const int n1 = min(n0 + AGG_NPW, NN);
        float4 bb = *reinterpret_cast<const float4*>(bias + c4);
        float s0 = 0.f, s1 = 0.f, s2 = 0.f, s3 = 0.f;
        float q0 = 0.f, q1 = 0.f, q2 = 0.f, q3 = 0.f;

        for (int node = n0; node < n1; node++) {
            int p = g_rowptr[node];
            const int e = g_rowptr[node + 1];
            float4 acc = make_float4(0.f, 0.f, 0.f, 0.f);
            for (; p + 3 < e; p += 4) {
                int i0 = __ldg(&g_colidx[p]);
                int i1 = __ldg(&g_colidx[p + 1]);
                int i2 = __ldg(&g_colidx[p + 2]);
                int i3 = __ldg(&g_colidx[p + 3]);
                float4 v0 = *reinterpret_cast<const float4*>(hc + (size_t)i0 * 256 + HH + c4);
                float4 v1 = *reinterpret_cast<const float4*>(hc + (size_t)i1 * 256 + HH + c4);
                float4 v2 = *reinterpret_cast<const float4*>(hc + (size_t)i2 * 256 + HH + c4);
                float4 v3 = *reinterpret_cast<const float4*>(hc + (size_t)i3 * 256 + HH + c4);
                acc.x += (v0.x + v1.x) + (v2.x + v3.x);
                acc.y += (v0.y + v1.y) + (v2.y + v3.y);
                acc.z += (v0.z + v1.z) + (v2.z + v3.z);
                acc.w += (v0.w + v1.w) + (v2.w + v3.w);
            }
            for (; p < e; p++) {
                int i0 = __ldg(&g_colidx[p]);
                float4 v0 = *reinterpret_cast<const float4*>(hc + (size_t)i0 * 256 + HH + c4);
                acc.x += v0.x; acc.y += v0.y; acc.z += v0.z; acc.w += v0.w;
            }
            float inv = 1.f / g_denom[node];
            float4 self = *reinterpret_cast<const float4*>(hc + (size_t)node * 256 + c4);
            float4 v;
            v.x = self.x + bb.x + acc.x * inv;
            v.y = self.y + bb.y + acc.y * inv;
            v.z = self.z + bb.z + acc.z * inv;
            v.w = self.w + bb.w + acc.w * inv;
            *reinterpret_cast<float4*>(hc + (size_t)node * 256 + c4) = v;
            s0 += v.x; s1 += v.y; s2 += v.z; s3 += v.w;
            q0 += v.x * v.x; q1 += v.y * v.y; q2 += v.z * v.z; q3 += v.w * v.w;
        }
        atomicAdd(&sst[c4 + 0], s0);
        atomicAdd(&sst[c4 + 1], s1);
        atomicAdd(&sst[c4 + 2], s2);
        atomicAdd(&sst[c4 + 3], s3);
        atomicAdd(&sst[HH + c4 + 0], q0);
        atomicAdd(&sst[HH + c4 + 1], q1);
        atomicAdd(&sst[HH + c4 + 2], q2);
        atomicAdd(&sst[HH + c4 + 3], q3);
    }
    __syncthreads();
    if (tid < 256) atomicAdd(&g_stats[tid], sst[tid]);
}

// head: pre stride 128, active cols = 64 (blockDim.x)
__global__ void k_combineH(float* __restrict__ pre, const float* __restrict__ bias,
                           int rows) {
    int c = threadIdx.x;                 // 64 threads
    int r0 = blockIdx.x * rows;
    int r1 = min(r0 + rows, NN);
    float bb = bias[c];
    float s = 0.f, s2 = 0.f;
    for (int r = r0; r < r1; r++) {
        float v = pre[(size_t)r * 128 + c] + bb;
        pre[(size_t)r * 128 + c] = v;
        s += v;
        s2 += v * v;
    }
    atomicAdd(&g_stats[c], s);
    atomicAdd(&g_stats[64 + c], s2);
}

// compute BN scale/offset, then self-zero stats for the next accumulation
__global__ void k_finalize(const float* __restrict__ gamma, const float* __restrict__ beta, int M) {
    int c = threadIdx.x;
    int Hc = blockDim.x;
    float inv_m = 1.f / (float)M;
    float mean = g_stats[c] * inv_m;
    float var = g_stats[Hc + c] * inv_m - mean * mean;
    float a = gamma[c] * rsqrtf(var + EPSV);
    g_ab[c] = a;
    g_ab[Hc + c] = beta[c] - mean * a;
    g_stats[c] = 0.f;
    g_stats[Hc + c] = 0.f;
}

// BN + (residual) + ReLU -> h
__global__ void k_norm(const float* __restrict__ pre, float* __restrict__ h,
                       const float* __restrict__ resid) {
    int i = blockIdx.x * blockDim.x + threadIdx.x;
    if (i >= NN * 32) return;
    int r = i >> 5, q = i & 31;
    float4 p = *reinterpret_cast<const float4*>(pre + (size_t)r * 256 + q * 4);
    float4 a = *reinterpret_cast<const float4*>(g_ab + q * 4);
    float4 b = *reinterpret_cast<const float4*>(g_ab + HH + q * 4);
    float4 v;
    v.x = fmaf(p.x, a.x, b.x); v.y = fmaf(p.y, a.y, b.y);
    v.z = fmaf(p.z, a.z, b.z); v.w = fmaf(p.w, a.w, b.w);
    if (resid) {
        float4 rr = *reinterpret_cast<const float4*>(resid + (size_t)r * HH + q * 4);
        v.x += rr.x; v.y += rr.y; v.z += rr.z; v.w += rr.w;
    }
    v.x = fmaxf(v.x, 0.f); v.y = fmaxf(v.y, 0.f);
    v.z = fmaxf(v.z, 0.f); v.w = fmaxf(v.w, 0.f);
    *reinterpret_cast<float4*>(h + (size_t)r * HH + q * 4) = v;
}

// final head: BN -> relu -> @W2 + b2, one warp per node (zpre stride 128)
__global__ void k_output(const float* __restrict__ zpre, const float* __restrict__ W2,
                         const float* __restrict__ b2, float* __restrict__ out) {
    int gtid = blockIdx.x * blockDim.x + threadIdx.x;
    int node = gtid >> 5;
    int lane = gtid & 31;
    if (node >= NN) return;
    float acc = 0.f;
    #pragma unroll
    for (int j = lane; j < 64; j += 32) {
        float v = fmaf(zpre[(size_t)node * 128 + j], g_ab[j], g_ab[64 + j]);
        v = fmaxf(v, 0.f);
        acc += v * W2[j];
    }
    #pragma unroll
    for (int o = 16; o; o >>= 1) acc += __shfl_xor_sync(0xFFFFFFFFu, acc, o);
    if (lane == 0) out[node] = acc + b2[0];
}

// ---------------- host orchestration ------------------------------------------
extern "C" void kernel_launch(void* const* d_in, const int* in_sizes, int n_in,
                              void* d_out, int out_size) {
    const float* inputs   = (const float*)d_in[0];
    const int*   graph    = (const int*)  d_in[1];
    const float* Wself0   = (const float*)d_in[2];
    const float* Wneigh0  = (const float*)d_in[3];
    const float* b0       = (const float*)d_in[4];
    const float* Wself    = (const float*)d_in[5];
    const float* Wneigh   = (const float*)d_in[6];
    const float* bvec     = (const float*)d_in[7];
    const float* bn_gamma = (const float*)d_in[8];
    const float* bn_beta  = (const float*)d_in[9];
    const float* W1       = (const float*)d_in[10];
    const float* b1       = (const float*)d_in[11];
    const float* bng1     = (const float*)d_in[12];
    const float* bnb1     = (const float*)d_in[13];
    const float* W2       = (const float*)d_in[14];
    const float* b2       = (const float*)d_in[15];
    float* out = (float*)d_out;

    float *h, *hc, *z;
    __nv_bfloat16 *B0h, *B0l, *BLh, *BLl, *BHh, *BHl;
    cudaGetSymbolAddress((void**)&h,   g_h);
    cudaGetSymbolAddress((void**)&hc,  g_hc);
    cudaGetSymbolAddress((void**)&z,   g_z);
    cudaGetSymbolAddress((void**)&B0h, g_B0h);
    cudaGetSymbolAddress((void**)&B0l, g_B0l);
    cudaGetSymbolAddress((void**)&BLh, g_BLh);
    cudaGetSymbolAddress((void**)&BLl, g_BLl);
    cudaGetSymbolAddress((void**)&BHh, g_BHh);
    cudaGetSymbolAddress((void**)&BHl, g_BHl);

    const int TB = 256;
    const int gN = (NN + TB - 1) / TB;
    const int gE = (EE + TB - 1) / TB;
    const dim3 gemmGrid(2, (NN + 127) / 128);
    const dim3 headGrid(1, (NN + 127) / 128);
    const int gNorm = (NN * 32 + TB - 1) / TB;
    const int gAgg = (NN + 127) / 128;

    cudaStream_t s2 = 0;
    cudaEvent_t evFork = 0, evJoin = 0;
    bool forked = (cudaStreamCreateWithFlags(&s2, cudaStreamNonBlocking) == cudaSuccess);
    if (forked) {
        cudaEventCreateWithFlags(&evFork, cudaEventDisableTiming);
        cudaEventCreateWithFlags(&evJoin, cudaEventDisableTiming);
    }
    cudaStream_t sc = forked ? s2 : 0;

    // ---- main stream: layer-0 weight conversion ----
    k_convW0<<<(256 * K0P + TB - 1) / TB, TB>>>(Wself0, Wneigh0);

    if (forked) {
        cudaEventRecord(evFork, 0);
        cudaStreamWaitEvent(s2, evFork, 0);
    }

    // side-stream weight conversions (submitted before GEMM so gemm_split is the
    // 4th launch -> ncu samples it)
    k_convWL<<<(3 * 256 * HH + TB - 1) / TB, TB, 0, sc>>>(Wself, Wneigh);
    k_convW1<<<(128 * HH + TB - 1) / TB, TB, 0, sc>>>(W1);

    // ---- layer 0 GEMM (concurrent with CSR branch below) ----
    gemm_split<<<gemmGrid, 256>>>(inputs, FIN, K0P, B0h, B0l, hc, NN, 256);

    // ---- CSR branch on side stream ----
    k_zero_deg<<<gN, TB, 0, sc>>>();
    k_count<<<gE, TB, 0, sc>>>(graph);
    k_scan1<<<(NN + 1023) / 1024, 1024, 0, sc>>>();
    k_scan2<<<1, 32, 0, sc>>>();
    k_scan3<<<gN, TB, 0, sc>>>();
    k_fill<<<gE, TB, 0, sc>>>(graph);
    if (forked) cudaEventRecord(evJoin, s2);

    if (forked) cudaStreamWaitEvent(0, evJoin, 0);

    // ---- layer 0 epilogue ----
    k_aggcomb<<<gAgg, 256>>>(hc, b0);
    k_finalize<<<1, HH>>>(bn_gamma, bn_beta, NN);
    k_norm<<<gNorm, TB>>>(hc, h, nullptr);

    // ---- layers 1..3 ----
    for (int l = 0; l < 3; l++) {
        gemm_split<<<gemmGrid, 256>>>(h, HH, HH,
                                      BLh + (size_t)l * 256 * HH,
                                      BLl + (size_t)l * 256 * HH,
                                      hc, NN, 256);
        k_aggcomb<<<gAgg, 256>>>(hc, bvec + (size_t)l * HH);
        k_finalize<<<1, HH>>>(bn_gamma + (size_t)(l + 1) * HH, bn_beta + (size_t)(l + 1) * HH, NN);
        k_norm<<<gNorm, TB>>>(hc, h, h);
    }

    // ---- head (tensor GEMM on padded W1, z stride 128) ----
    gemm_split<<<headGrid, 256>>>(h, HH, HH, BHh, BHl, z, NN, 128);
    k_combineH<<<(NN + 127) / 128, 64>>>(z, b1, 128);
    k_finalize<<<1, 64>>>(bng1, bnb1, NN);
    k_output<<<(NN * 32 + TB - 1) / TB, TB>>>(z, W2, b2, out);

    (void)in_sizes; (void)n_in; (void)out_size;
}

// round 13
// speedup vs baseline: 1.0963x; 1.0963x over previous
#include <cuda_runtime.h>
#include <cuda_bf16.h>
#include <math.h>
#include <stdint.h>

#define NN   100000
#define EE   1600000
#define FIN  700
#define K0P  704
#define HH   128
#define EPSV 1e-5f

// ---------------- scratch (static device globals; zero-init, no runtime alloc) ----
__device__ float g_h  [(size_t)NN * HH];
__device__ float g_hc [(size_t)NN * 256];        // [self(128) | neigh(128)] per row
__device__ float g_z  [(size_t)NN * 128];        // head pre-activations (stride 128)
__device__ float g_denom[NN];
__device__ int   g_deg[NN];
__device__ int   g_rowptr[NN + 1];
__device__ int   g_colidx[EE];
__device__ int   g_bsums[128];
__device__ __align__(16) float g_stats[256];
__device__ __align__(16) float g_ab[256];

// bf16 split weights (A operands are split in-GEMM)
__device__ __nv_bfloat16 g_B0h[256 * K0P];
__device__ __nv_bfloat16 g_B0l[256 * K0P];
__device__ __nv_bfloat16 g_BLh[3 * 256 * HH];
__device__ __nv_bfloat16 g_BLl[3 * 256 * HH];
__device__ __nv_bfloat16 g_BHh[128 * HH];        // head W1 padded to 128 cols
__device__ __nv_bfloat16 g_BHl[128 * HH];

// ---------------- helpers ------------------------------------------------------
__device__ __forceinline__ void split_bf16(float x, __nv_bfloat16& h, __nv_bfloat16& l) {
    h = __float2bfloat16(x);
    l = __float2bfloat16(x - __bfloat162float(h));
}
__device__ __forceinline__ uint32_t pkbf2(__nv_bfloat16 a, __nv_bfloat16 b) {
    __nv_bfloat162 t = __halves2bfloat162(a, b);
    return *reinterpret_cast<uint32_t*>(&t);
}
__device__ __forceinline__ void cp16(uint32_t s, const void* g) {
    asm volatile("cp.async.cg.shared.global [%0], [%1], 16;" :: "r"(s), "l"(g));
}
__device__ __forceinline__ void ldsm4(uint32_t& r0, uint32_t& r1, uint32_t& r2, uint32_t& r3, uint32_t a) {
    asm volatile("ldmatrix.sync.aligned.m8n8.x4.shared.b16 {%0,%1,%2,%3}, [%4];"
                 : "=r"(r0), "=r"(r1), "=r"(r2), "=r"(r3) : "r"(a));
}
__device__ __forceinline__ void mma16816(float* c, const uint32_t* a, const uint32_t* b) {
    asm volatile("mma.sync.aligned.m16n8k16.row.col.f32.bf16.bf16.f32 "
                 "{%0,%1,%2,%3}, {%4,%5,%6,%7}, {%8,%9}, {%0,%1,%2,%3};"
                 : "+f"(c[0]), "+f"(c[1]), "+f"(c[2]), "+f"(c[3])
                 : "r"(a[0]), "r"(a[1]), "r"(a[2]), "r"(a[3]), "r"(b[0]), "r"(b[1]));
}

// ---------------- CSR construction --------------------------------------------
__global__ void k_zero_deg() {
    int i = blockIdx.x * blockDim.x + threadIdx.x;
    if (i < NN) g_deg[i] = 0;
}
__global__ void k_count(const int* __restrict__ graph) {
    int e = blockIdx.x * blockDim.x + threadIdx.x;
    if (e < EE) atomicAdd(&g_deg[graph[2 * e + 1]], 1);
}
__global__ void k_scan1() {
    __shared__ int s[1024];
    int tid = threadIdx.x;
    int i = blockIdx.x * 1024 + tid;
    int v = (i < NN) ? g_deg[i] : 0;
    s[tid] = v;
    __syncthreads();
    #pragma unroll
    for (int off = 1; off < 1024; off <<= 1) {
        int t = (tid >= off) ? s[tid - off] : 0;
        __syncthreads();
        s[tid] += t;
        __syncthreads();
    }
    if (i < NN) g_rowptr[i + 1] = s[tid];
    if (tid == 1023) g_bsums[blockIdx.x] = s[1023];
}
__global__ void k_scan2() {
    if (threadIdx.x == 0) {
        const int nb = (NN + 1023) / 1024;
        int acc = 0;
        for (int i = 0; i < nb; i++) { int t = g_bsums[i]; g_bsums[i] = acc; acc += t; }
    }
}
__global__ void k_scan3() {
    int i = blockIdx.x * blockDim.x + threadIdx.x;
    if (i >= NN) return;
    g_rowptr[i + 1] += g_bsums[i >> 10];
    if (i == 0) g_rowptr[0] = 0;
    int d = g_deg[i];
    g_denom[i] = (float)((d > 1) ? d : 1);
    g_deg[i] = 0;
}
__global__ void k_fill(const int* __restrict__ graph) {
    int e = blockIdx.x * blockDim.x + threadIdx.x;
    if (e >= EE) return;
    int src = graph[2 * e + 0];
    int dst = graph[2 * e + 1];
    int pos = g_rowptr[dst] + atomicAdd(&g_deg[dst], 1);
    g_colidx[pos] = src;
}

// ---------------- weight conversion --------------------------------------------
__global__ void k_convW0(const float* __restrict__ Ws, const float* __restrict__ Wn) {
    int idx = blockIdx.x * blockDim.x + threadIdx.x;
    if (idx >= 256 * K0P) return;
    int n = idx / K0P, k = idx % K0P;
    float v = 0.f;
    if (k < FIN) v = (n < HH) ? Ws[(size_t)k * HH + n] : Wn[(size_t)k * HH + (n - HH)];
    split_bf16(v, g_B0h[idx], g_B0l[idx]);
}
__global__ void k_convWL(const float* __restrict__ Ws, const float* __restrict__ Wn) {
    int idx = blockIdx.x * blockDim.x + threadIdx.x;
    if (idx >= 3 * 256 * HH) return;
    int l = idx / (256 * HH);
    int rem = idx % (256 * HH);
    int n = rem / HH, k = rem % HH;
    float v = (n < HH) ? Ws[(size_t)l * HH * HH + k * HH + n]
                       : Wn[(size_t)l * HH * HH + k * HH + (n - HH)];
    split_bf16(v, g_BLh[idx], g_BLl[idx]);
}
__global__ void k_convW1(const float* __restrict__ W1) {
    int idx = blockIdx.x * blockDim.x + threadIdx.x;
    if (idx >= 128 * HH) return;
    int n = idx / HH, k = idx % HH;
    float v = (n < 64) ? W1[(size_t)k * 64 + n] : 0.f;
    split_bf16(v, g_BHh[idx], g_BHl[idx]);
}

// ---------------- split-precision tensor GEMM, fp32 A fed in-kernel ------------
// (byte-exact R11 configuration: BM=128, BN=128, BK=16, 2-stage, static 48KB smem)
#define TILE_B 6144
#define STAGE_B 24576
__global__ void __launch_bounds__(256) gemm_split(
    const float* __restrict__ A, int K, int Kpad,
    const __nv_bfloat16* __restrict__ Bh0, const __nv_bfloat16* __restrict__ Bl0,
    float* __restrict__ C, int M, int NCs)
{
    __shared__ __align__(16) char smem[49152];
    const uint32_t sb = (uint32_t)__cvta_generic_to_shared(smem);
    const int tid = threadIdx.x;
    const int bx = blockIdx.x, by = blockIdx.y;
    const int row0 = by * 128;
    const __nv_bfloat16* Bh = Bh0 + (size_t)bx * 128 * Kpad;
    const __nv_bfloat16* Bl = Bl0 + (size_t)bx * 128 * Kpad;
    const int KT = Kpad >> 4;

    const int ar = tid >> 1, aq = tid & 1;
    const int agr = row0 + ar;
    const float* Arow = A + (size_t)agr * K;

    float4 hv0, hv1;
    float4 nv0, nv1;

    auto ldgA = [&](int kt, float4& v0, float4& v1) {
        v0 = make_float4(0.f, 0.f, 0.f, 0.f);
        v1 = v0;
        int kb = kt * 16 + aq * 8;
        if (agr < M) {
            if (kb + 3 < K) v0 = *reinterpret_cast<const float4*>(Arow + kb);
            if (kb + 7 < K) v1 = *reinterpret_cast<const float4*>(Arow + kb + 4);
        }
    };
    auto stsA = [&](int stage, float4 v0, float4 v1) {
        float f[8] = {v0.x, v0.y, v0.z, v0.w, v1.x, v1.y, v1.z, v1.w};
        __nv_bfloat16 hh[8], ll[8];
        #pragma unroll
        for (int i = 0; i < 8; i++) split_bf16(f[i], hh[i], ll[i]);
        uint4 hvv, lvv;
        hvv.x = pkbf2(hh[0], hh[1]); hvv.y = pkbf2(hh[2], hh[3]);
        hvv.z = pkbf2(hh[4], hh[5]); hvv.w = pkbf2(hh[6], hh[7]);
        lvv.x = pkbf2(ll[0], ll[1]); lvv.y = pkbf2(ll[2], ll[3]);
        lvv.z = pkbf2(ll[4], ll[5]); lvv.w = pkbf2(ll[6], ll[7]);
        char* dst = smem + stage * STAGE_B + ar * 48 + aq * 16;
        *reinterpret_cast<uint4*>(dst) = hvv;
        *reinterpret_cast<uint4*>(dst + TILE_B) = lvv;
    };
    auto cpB = [&](int kt) {
        uint32_t base = sb + (uint32_t)(kt & 1) * STAGE_B + 2u * TILE_B;
        int r = tid >> 1, q = tid & 1;
        uint32_t so = base + (uint32_t)(r * 48 + q * 16);
        size_t gb = (size_t)r * Kpad + kt * 16 + q * 8;
        cp16(so, Bh + gb);
        cp16(so + TILE_B, Bl + gb);
        asm volatile("cp.async.commit_group;");
    };

    {
        float4 a0, a1;
        ldgA(0, a0, a1);
        ldgA(1, hv0, hv1);
        cpB(0);
        cpB(1);
        stsA(0, a0, a1);
    }

    const int lane = tid & 31, w = tid >> 5;
    const int wm = w >> 2, wn = w & 3;
    const int lr = lane >> 2, lc = lane & 3;
    const int mat = lane >> 3, r8 = lane & 7;

    float acc[4][4][4];
    #pragma unroll
    for (int a = 0; a < 4; a++)
        #pragma unroll
        for (int b = 0; b < 4; b++)
            #pragma unroll
            for (int d = 0; d < 4; d++) acc[a][b][d] = 0.f;

    for (int kt = 0; kt < KT; ++kt) {
        if (kt < KT - 1) asm volatile("cp.async.wait_group 1;");
        else             asm volatile("cp.async.wait_group 0;");
        __syncthreads();

        if (kt + 1 < KT) stsA((kt + 1) & 1, hv0, hv1);
        if (kt + 2 < KT) ldgA(kt + 2, nv0, nv1);

        uint32_t base = sb + (uint32_t)(kt & 1) * STAGE_B;

        uint32_t bh[2][4], bl[2][4];
        #pragma unroll
        for (int p = 0; p < 2; p++) {
            int brow = wn * 32 + p * 16 + r8 + (mat >> 1) * 8;
            uint32_t addr = base + 2u * TILE_B + (uint32_t)(brow * 48 + ((mat & 1) * 8) * 2);
            ldsm4(bh[p][0], bh[p][1], bh[p][2], bh[p][3], addr);
            ldsm4(bl[p][0], bl[p][1], bl[p][2], bl[p][3], addr + TILE_B);
        }
        #pragma unroll
        for (int mf = 0; mf < 4; ++mf) {
            int arow = wm * 64 + mf * 16 + r8 + (mat & 1) * 8;
            uint32_t aaddr = base + (uint32_t)(arow * 48 + ((mat >> 1) * 8) * 2);
            uint32_t ahr[4], alr[4];
            ldsm4(ahr[0], ahr[1], ahr[2], ahr[3], aaddr);
            ldsm4(alr[0], alr[1], alr[2], alr[3], aaddr + TILE_B);
            #pragma unroll
            for (int nf = 0; nf < 4; ++nf) {
                const uint32_t* bhp = &bh[nf >> 1][(nf & 1) * 2];
                const uint32_t* blp = &bl[nf >> 1][(nf & 1) * 2];
                mma16816(acc[mf][nf], ahr, bhp);
                mma16816(acc[mf][nf], alr, bhp);
                mma16816(acc[mf][nf], ahr, blp);
            }
        }
        __syncthreads();
        if (kt + 2 < KT) {
            cpB(kt + 2);
            hv0 = nv0; hv1 = nv1;
        }
    }

    #pragma unroll
    for (int mf = 0; mf < 4; ++mf) {
        #pragma unroll
        for (int nf = 0; nf < 4; ++nf) {
            int r = row0 + wm * 64 + mf * 16 + lr;
            int cc = bx * 128 + wn * 32 + nf * 8 + lc * 2;
            if (r < M)
                *reinterpret_cast<float2*>(C + (size_t)r * NCs + cc) =
                    make_float2(acc[mf][nf][0], acc[mf][nf][1]);
            if (r + 8 < M)
                *reinterpret_cast<float2*>(C + (size_t)(r + 8) * NCs + cc) =
                    make_float2(acc[mf][nf][2], acc[mf][nf][3]);
        }
    }
}

// ---------------- fused CSR gather + bias + BN stats (warp-per-node) -----------
// AGG_NPW=8: 12.5k warps smooth the degree-skew tail (vs 6.25k at NPW=16).
#define AGG_NPW 8
__global__ void __launch_bounds__(256) k_aggcomb(float* __restrict__ hc,
                                                 const float* __restrict__ bias) {
    __shared__ float sst[256];
    const int tid = threadIdx.x;
    const int lane = tid & 31;
    const int gw = blockIdx.x * 8 + (tid >> 5);
    const int c4 = lane * 4;
    const int n0 = gw * AGG_NPW;
    if (tid < 256) sst[tid] = 0.f;
    __syncthreads();

    if (n0 < NN) {
        const int n1 = min(n0 + AGG_NPW, NN);
        float4 bb = *reinterpret_cast<const float4*>(bias + c4);
        float s0 = 0.f, s1 = 0.f, s2 = 0.f, s3 = 0.f;
        float q0 = 0.f, q1 = 0.f, q2 = 0.f, q3 = 0.f;

        for (int node = n0; node < n1; node++) {
            int p = g_rowptr[node];
            const int e = g_rowptr[node + 1];
            float4 acc = make_float4(0.f, 0.f, 0.f, 0.f);
            for (; p + 3 < e; p += 4) {
                int i0 = __ldg(&g_colidx[p]);
                int i1 = __ldg(&g_colidx[p + 1]);
                int i2 = __ldg(&g_colidx[p + 2]);
                int i3 = __ldg(&g_colidx[p + 3]);
                float4 v0 = *reinterpret_cast<const float4*>(hc + (size_t)i0 * 256 + HH + c4);
                float4 v1 = *reinterpret_cast<const float4*>(hc + (size_t)i1 * 256 + HH + c4);
                float4 v2 = *reinterpret_cast<const float4*>(hc + (size_t)i2 * 256 + HH + c4);
                float4 v3 = *reinterpret_cast<const float4*>(hc + (size_t)i3 * 256 + HH + c4);
                acc.x += (v0.x + v1.x) + (v2.x + v3.x);
                acc.y += (v0.y + v1.y) + (v2.y + v3.y);
                acc.z += (v0.z + v1.z) + (v2.z + v3.z);
                acc.w += (v0.w + v1.w) + (v2.w + v3.w);
            }
            for (; p < e; p++) {
                int i0 = __ldg(&g_colidx[p]);
                float4 v0 = *reinterpret_cast<const float4*>(hc + (size_t)i0 * 256 + HH + c4);
                acc.x += v0.x; acc.y += v0.y; acc.z += v0.z; acc.w += v0.w;
            }
            float inv = 1.f / g_denom[node];
            float4 self = *reinterpret_cast<const float4*>(hc + (size_t)node * 256 + c4);
            float4 v;
            v.x = self.x + bb.x + acc.x * inv;
            v.y = self.y + bb.y + acc.y * inv;
            v.z = self.z + bb.z + acc.z * inv;
            v.w = self.w + bb.w + acc.w * inv;
            *reinterpret_cast<float4*>(hc + (size_t)node * 256 + c4) = v;
            s0 += v.x; s1 += v.y; s2 += v.z; s3 += v.w;
            q0 += v.x * v.x; q1 += v.y * v.y; q2 += v.z * v.z; q3 += v.w * v.w;
        }
        atomicAdd(&sst[c4 + 0], s0);
        atomicAdd(&sst[c4 + 1], s1);
        atomicAdd(&sst[c4 + 2], s2);
        atomicAdd(&sst[c4 + 3], s3);
        atomicAdd(&sst[HH + c4 + 0], q0);
        atomicAdd(&sst[HH + c4 + 1], q1);
        atomicAdd(&sst[HH + c4 + 2], q2);
        atomicAdd(&sst[HH + c4 + 3], q3);
    }
    __syncthreads();
    if (tid < 256) atomicAdd(&g_stats[tid], sst[tid]);
}

// head: pre stride 128, active cols = 64 (blockDim.x)
__global__ void k_combineH(float* __restrict__ pre, const float* __restrict__ bias,
                           int rows) {
    int c = threadIdx.x;                 // 64 threads
    int r0 = blockIdx.x * rows;
    int r1 = min(r0 + rows, NN);
    float bb = bias[c];
    float s = 0.f, s2 = 0.f;
    for (int r = r0; r < r1; r++) {
        float v = pre[(size_t)r * 128 + c] + bb;
        pre[(size_t)r * 128 + c] = v;
        s += v;
        s2 += v * v;
    }
    atomicAdd(&g_stats[c], s);
    atomicAdd(&g_stats[64 + c], s2);
}

// compute BN scale/offset, then self-zero stats for the next accumulation
__global__ void k_finalize(const float* __restrict__ gamma, const float* __restrict__ beta, int M) {
    int c = threadIdx.x;
    int Hc = blockDim.x;
    float inv_m = 1.f / (float)M;
    float mean = g_stats[c] * inv_m;
    float var = g_stats[Hc + c] * inv_m - mean * mean;
    float a = gamma[c] * rsqrtf(var + EPSV);
    g_ab[c] = a;
    g_ab[Hc + c] = beta[c] - mean * a;
    g_stats[c] = 0.f;
    g_stats[Hc + c] = 0.f;
}

// BN + (residual) + ReLU -> h
__global__ void k_norm(const float* __restrict__ pre, float* __restrict__ h,
                       const float* __restrict__ resid) {
    int i = blockIdx.x * blockDim.x + threadIdx.x;
    if (i >= NN * 32) return;
    int r = i >> 5, q = i & 31;
    float4 p = *reinterpret_cast<const float4*>(pre + (size_t)r * 256 + q * 4);
    float4 a = *reinterpret_cast<const float4*>(g_ab + q * 4);
    float4 b = *reinterpret_cast<const float4*>(g_ab + HH + q * 4);
    float4 v;
    v.x = fmaf(p.x, a.x, b.x); v.y = fmaf(p.y, a.y, b.y);
    v.z = fmaf(p.z, a.z, b.z); v.w = fmaf(p.w, a.w, b.w);
    if (resid) {
        float4 rr = *reinterpret_cast<const float4*>(resid + (size_t)r * HH + q * 4);
        v.x += rr.x; v.y += rr.y; v.z += rr.z; v.w += rr.w;
    }
    v.x = fmaxf(v.x, 0.f); v.y = fmaxf(v.y, 0.f);
    v.z = fmaxf(v.z, 0.f); v.w = fmaxf(v.w, 0.f);
    *reinterpret_cast<float4*>(h + (size_t)r * HH + q * 4) = v;
}

// final head: BN -> relu -> @W2 + b2, one warp per node (zpre stride 128)
__global__ void k_output(const float* __restrict__ zpre, const float* __restrict__ W2,
                         const float* __restrict__ b2, float* __restrict__ out) {
    int gtid = blockIdx.x * blockDim.x + threadIdx.x;
    int node = gtid >> 5;
    int lane = gtid & 31;
    if (node >= NN) return;
    float acc = 0.f;
    #pragma unroll
    for (int j = lane; j < 64; j += 32) {
        float v = fmaf(zpre[(size_t)node * 128 + j], g_ab[j], g_ab[64 + j]);
        v = fmaxf(v, 0.f);
        acc += v * W2[j];
    }
    #pragma unroll
    for (int o = 16; o; o >>= 1) acc += __shfl_xor_sync(0xFFFFFFFFu, acc, o);
    if (lane == 0) out[node] = acc + b2[0];
}

// ---------------- host orchestration ------------------------------------------
extern "C" void kernel_launch(void* const* d_in, const int* in_sizes, int n_in,
                              void* d_out, int out_size) {
    const float* inputs   = (const float*)d_in[0];
    const int*   graph    = (const int*)  d_in[1];
    const float* Wself0   = (const float*)d_in[2];
    const float* Wneigh0  = (const float*)d_in[3];
    const float* b0       = (const float*)d_in[4];
    const float* Wself    = (const float*)d_in[5];
    const float* Wneigh   = (const float*)d_in[6];
    const float* bvec     = (const float*)d_in[7];
    const float* bn_gamma = (const float*)d_in[8];
    const float* bn_beta  = (const float*)d_in[9];
    const float* W1       = (const float*)d_in[10];
    const float* b1       = (const float*)d_in[11];
    const float* bng1     = (const float*)d_in[12];
    const float* bnb1     = (const float*)d_in[13];
    const float* W2       = (const float*)d_in[14];
    const float* b2       = (const float*)d_in[15];
    float* out = (float*)d_out;

    float *h, *hc, *z;
    __nv_bfloat16 *B0h, *B0l, *BLh, *BLl, *BHh, *BHl;
    cudaGetSymbolAddress((void**)&h,   g_h);
    cudaGetSymbolAddress((void**)&hc,  g_hc);
    cudaGetSymbolAddress((void**)&z,   g_z);
    cudaGetSymbolAddress((void**)&B0h, g_B0h);
    cudaGetSymbolAddress((void**)&B0l, g_B0l);
    cudaGetSymbolAddress((void**)&BLh, g_BLh);
    cudaGetSymbolAddress((void**)&BLl, g_BLl);
    cudaGetSymbolAddress((void**)&BHh, g_BHh);
    cudaGetSymbolAddress((void**)&BHl, g_BHl);

    const int TB = 256;
    const int gN = (NN + TB - 1) / TB;
    const int gE = (EE + TB - 1) / TB;
    const dim3 gemmGrid(2, (NN + 127) / 128);
    const dim3 headGrid(1, (NN + 127) / 128);
    const int gNorm = (NN * 32 + TB - 1) / TB;
    const int gAgg = (NN + 8 * AGG_NPW - 1) / (8 * AGG_NPW);

    cudaStream_t s2 = 0;
    cudaEvent_t evFork = 0, evJoin = 0;
    bool forked = (cudaStreamCreateWithFlags(&s2, cudaStreamNonBlocking) == cudaSuccess);
    if (forked) {
        cudaEventCreateWithFlags(&evFork, cudaEventDisableTiming);
        cudaEventCreateWithFlags(&evJoin, cudaEventDisableTiming);
    }
    cudaStream_t sc = forked ? s2 : 0;

    // ---- main stream: layer-0 weight conversion ----
    k_convW0<<<(256 * K0P + TB - 1) / TB, TB>>>(Wself0, Wneigh0);

    if (forked) {
        cudaEventRecord(evFork, 0);
        cudaStreamWaitEvent(s2, evFork, 0);
    }

    // ---- CSR branch (overlaps layer-0 GEMM) ----
    k_convWL<<<(3 * 256 * HH + TB - 1) / TB, TB, 0, sc>>>(Wself, Wneigh);
    k_convW1<<<(128 * HH + TB - 1) / TB, TB, 0, sc>>>(W1);
    k_zero_deg<<<gN, TB, 0, sc>>>();
    k_count<<<gE, TB, 0, sc>>>(graph);
    k_scan1<<<(NN + 1023) / 1024, 1024, 0, sc>>>();
    k_scan2<<<1, 32, 0, sc>>>();
    k_scan3<<<gN, TB, 0, sc>>>();
    k_fill<<<gE, TB, 0, sc>>>(graph);
    if (forked) cudaEventRecord(evJoin, s2);

    // ---- layer 0 GEMM (concurrent with CSR branch) ----
    gemm_split<<<gemmGrid, 256>>>(inputs, FIN, K0P, B0h, B0l, hc, NN, 256);

    if (forked) cudaStreamWaitEvent(0, evJoin, 0);

    // ---- layer 0 epilogue ----
    k_aggcomb<<<gAgg, 256>>>(hc, b0);
    k_finalize<<<1, HH>>>(bn_gamma, bn_beta, NN);
    k_norm<<<gNorm, TB>>>(hc, h, nullptr);

    // ---- layers 1..3 ----
    for (int l = 0; l < 3; l++) {
        gemm_split<<<gemmGrid, 256>>>(h, HH, HH,
                                      BLh + (size_t)l * 256 * HH,
                                      BLl + (size_t)l * 256 * HH,
                                      hc, NN, 256);
        k_aggcomb<<<gAgg, 256>>>(hc, bvec + (size_t)l * HH);
        k_finalize<<<1, HH>>>(bn_gamma + (size_t)(l + 1) * HH, bn_beta + (size_t)(l + 1) * HH, NN);
        k_norm<<<gNorm, TB>>>(hc, h, h);
    }

    // ---- head (tensor GEMM on padded W1, z stride 128) ----
    gemm_split<<<headGrid, 256>>>(h, HH, HH, BHh, BHl, z, NN, 128);
    k_combineH<<<(NN + 127) / 128, 64>>>(z, b1, 128);
    k_finalize<<<1, 64>>>(bng1, bnb1, NN);
    k_output<<<(NN * 32 + TB - 1) / TB, TB>>>(z, W2, b2, out);

    (void)in_sizes; (void)n_in; (void)out_size;
}

// round 15
// speedup vs baseline: 1.1542x; 1.0527x over previous
#include <cuda_runtime.h>
#include <cuda_bf16.h>
#include <cuda_fp16.h>
#include <math.h>
#include <stdint.h>

#define NN   100000
#define EE   1600000
#define FIN  700
#define K0P  704
#define HH   128
#define EPSV 1e-5f

// ---------------- scratch (static device globals; zero-init, no runtime alloc) ----
__device__ float g_h  [(size_t)NN * HH];
__device__ float g_hc [(size_t)NN * 256];        // [self(128) | neigh(unused on fp16 path)]
__device__ __half g_hnb[(size_t)NN * HH];        // neigh half as fp16 (gather source)
__device__ float g_z  [(size_t)NN * 128];        // head pre-activations (stride 128)
__device__ float g_denom[NN];
__device__ int   g_deg[NN];
__device__ int   g_rowptr[NN + 1];
__device__ int   g_colidx[EE];
__device__ int   g_bsums[128];
__device__ __align__(16) float g_stats[256];
__device__ __align__(16) float g_ab[256];

// bf16 split weights (A operands are split in-GEMM)
__device__ __nv_bfloat16 g_B0h[256 * K0P];
__device__ __nv_bfloat16 g_B0l[256 * K0P];
__device__ __nv_bfloat16 g_BLh[3 * 256 * HH];
__device__ __nv_bfloat16 g_BLl[3 * 256 * HH];
__device__ __nv_bfloat16 g_BHh[128 * HH];        // head W1 padded to 128 cols
__device__ __nv_bfloat16 g_BHl[128 * HH];

// ---------------- helpers ------------------------------------------------------
__device__ __forceinline__ void split_bf16(float x, __nv_bfloat16& h, __nv_bfloat16& l) {
    h = __float2bfloat16(x);
    l = __float2bfloat16(x - __bfloat162float(h));
}
__device__ __forceinline__ uint32_t pkbf2(__nv_bfloat16 a, __nv_bfloat16 b) {
    __nv_bfloat162 t = __halves2bfloat162(a, b);
    return *reinterpret_cast<uint32_t*>(&t);
}
__device__ __forceinline__ float4 ld_hf4(const __half* p) {
    uint2 raw = *reinterpret_cast<const uint2*>(p);
    __half2 a = *reinterpret_cast<__half2*>(&raw.x);
    __half2 b = *reinterpret_cast<__half2*>(&raw.y);
    float2 fa = __half22float2(a), fb = __half22float2(b);
    return make_float4(fa.x, fa.y, fb.x, fb.y);
}
__device__ __forceinline__ void cp16(uint32_t s, const void* g) {
    asm volatile("cp.async.cg.shared.global [%0], [%1], 16;" :: "r"(s), "l"(g));
}
__device__ __forceinline__ void ldsm4(uint32_t& r0, uint32_t& r1, uint32_t& r2, uint32_t& r3, uint32_t a) {
    asm volatile("ldmatrix.sync.aligned.m8n8.x4.shared.b16 {%0,%1,%2,%3}, [%4];"
                 : "=r"(r0), "=r"(r1), "=r"(r2), "=r"(r3) : "r"(a));
}
__device__ __forceinline__ void mma16816(float* c, const uint32_t* a, const uint32_t* b) {
    asm volatile("mma.sync.aligned.m16n8k16.row.col.f32.bf16.bf16.f32 "
                 "{%0,%1,%2,%3}, {%4,%5,%6,%7}, {%8,%9}, {%0,%1,%2,%3};"
                 : "+f"(c[0]), "+f"(c[1]), "+f"(c[2]), "+f"(c[3])
                 : "r"(a[0]), "r"(a[1]), "r"(a[2]), "r"(a[3]), "r"(b[0]), "r"(b[1]));
}

// ---------------- CSR construction --------------------------------------------
__global__ void k_zero_deg() {
    int i = blockIdx.x * blockDim.x + threadIdx.x;
    if (i < NN) g_deg[i] = 0;
}
__global__ void k_count(const int* __restrict__ graph) {
    int e = blockIdx.x * blockDim.x + threadIdx.x;
    if (e < EE) atomicAdd(&g_deg[graph[2 * e + 1]], 1);
}
__global__ void k_scan1() {
    __shared__ int s[1024];
    int tid = threadIdx.x;
    int i = blockIdx.x * 1024 + tid;
    int v = (i < NN) ? g_deg[i] : 0;
    s[tid] = v;
    __syncthreads();
    #pragma unroll
    for (int off = 1; off < 1024; off <<= 1) {
        int t = (tid >= off) ? s[tid - off] : 0;
        __syncthreads();
        s[tid] += t;
        __syncthreads();
    }
    if (i < NN) g_rowptr[i + 1] = s[tid];
    if (tid == 1023) g_bsums[blockIdx.x] = s[1023];
}
__global__ void k_scan2() {
    if (threadIdx.x == 0) {
        const int nb = (NN + 1023) / 1024;
        int acc = 0;
        for (int i = 0; i < nb; i++) { int t = g_bsums[i]; g_bsums[i] = acc; acc += t; }
    }
}
__global__ void k_scan3() {
    int i = blockIdx.x * blockDim.x + threadIdx.x;
    if (i >= NN) return;
    g_rowptr[i + 1] += g_bsums[i >> 10];
    if (i == 0) g_rowptr[0] = 0;
    int d = g_deg[i];
    g_denom[i] = (float)((d > 1) ? d : 1);
    g_deg[i] = 0;
}
__global__ void k_fill(const int* __restrict__ graph) {
    int e = blockIdx.x * blockDim.x + threadIdx.x;
    if (e >= EE) return;
    int src = graph[2 * e + 0];
    int dst = graph[2 * e + 1];
    int pos = g_rowptr[dst] + atomicAdd(&g_deg[dst], 1);
    g_colidx[pos] = src;
}

// ---------------- weight conversion --------------------------------------------
__global__ void k_convW0(const float* __restrict__ Ws, const float* __restrict__ Wn) {
    int idx = blockIdx.x * blockDim.x + threadIdx.x;
    if (idx >= 256 * K0P) return;
    int n = idx / K0P, k = idx % K0P;
    float v = 0.f;
    if (k < FIN) v = (n < HH) ? Ws[(size_t)k * HH + n] : Wn[(size_t)k * HH + (n - HH)];
    split_bf16(v, g_B0h[idx], g_B0l[idx]);
}
__global__ void k_convWL(const float* __restrict__ Ws, const float* __restrict__ Wn) {
    int idx = blockIdx.x * blockDim.x + threadIdx.x;
    if (idx >= 3 * 256 * HH) return;
    int l = idx / (256 * HH);
    int rem = idx % (256 * HH);
    int n = rem / HH, k = rem % HH;
    float v = (n < HH) ? Ws[(size_t)l * HH * HH + k * HH + n]
                       : Wn[(size_t)l * HH * HH + k * HH + (n - HH)];
    split_bf16(v, g_BLh[idx], g_BLl[idx]);
}
__global__ void k_convW1(const float* __restrict__ W1) {
    int idx = blockIdx.x * blockDim.x + threadIdx.x;
    if (idx >= 128 * HH) return;
    int n = idx / HH, k = idx % HH;
    float v = (n < 64) ? W1[(size_t)k * 64 + n] : 0.f;
    split_bf16(v, g_BHh[idx], g_BHl[idx]);
}

// ---------------- split-precision tensor GEMM, fp32 A fed in-kernel ------------
// R11 inner loop (frozen). When nbf!=0 and bx==1, the epilogue writes the
// neighbor-half output as fp16 into g_hnb (gather source) instead of fp32 hc.
#define TILE_B 6144
#define STAGE_B 24576
__global__ void __launch_bounds__(256) gemm_split(
    const float* __restrict__ A, int K, int Kpad,
    const __nv_bfloat16* __restrict__ Bh0, const __nv_bfloat16* __restrict__ Bl0,
    float* __restrict__ C, int M, int NCs, int nbf)
{
    __shared__ __align__(16) char smem[49152];
    const uint32_t sb = (uint32_t)__cvta_generic_to_shared(smem);
    const int tid = threadIdx.x;
    const int bx = blockIdx.x, by = blockIdx.y;
    const int row0 = by * 128;
    const __nv_bfloat16* Bh = Bh0 + (size_t)bx * 128 * Kpad;
    const __nv_bfloat16* Bl = Bl0 + (size_t)bx * 128 * Kpad;
    const int KT = Kpad >> 4;

    const int ar = tid >> 1, aq = tid & 1;
    const int agr = row0 + ar;
    const float* Arow = A + (size_t)agr * K;

    float4 hv0, hv1;
    float4 nv0, nv1;

    auto ldgA = [&](int kt, float4& v0, float4& v1) {
        v0 = make_float4(0.f, 0.f, 0.f, 0.f);
        v1 = v0;
        int kb = kt * 16 + aq * 8;
        if (agr < M) {
            if (kb + 3 < K) v0 = *reinterpret_cast<const float4*>(Arow + kb);
            if (kb + 7 < K) v1 = *reinterpret_cast<const float4*>(Arow + kb + 4);
        }
    };
    auto stsA = [&](int stage, float4 v0, float4 v1) {
        float f[8] = {v0.x, v0.y, v0.z, v0.w, v1.x, v1.y, v1.z, v1.w};
        __nv_bfloat16 hh[8], ll[8];
        #pragma unroll
        for (int i = 0; i < 8; i++) split_bf16(f[i], hh[i], ll[i]);
        uint4 hvv, lvv;
        hvv.x = pkbf2(hh[0], hh[1]); hvv.y = pkbf2(hh[2], hh[3]);
        hvv.z = pkbf2(hh[4], hh[5]); hvv.w = pkbf2(hh[6], hh[7]);
        lvv.x = pkbf2(ll[0], ll[1]); lvv.y = pkbf2(ll[2], ll[3]);
        lvv.z = pkbf2(ll[4], ll[5]); lvv.w = pkbf2(ll[6], ll[7]);
        char* dst = smem + stage * STAGE_B + ar * 48 + aq * 16;
        *reinterpret_cast<uint4*>(dst) = hvv;
        *reinterpret_cast<uint4*>(dst + TILE_B) = lvv;
    };
    auto cpB = [&](int kt) {
        uint32_t base = sb + (uint32_t)(kt & 1) * STAGE_B + 2u * TILE_B;
        int r = tid >> 1, q = tid & 1;
        uint32_t so = base + (uint32_t)(r * 48 + q * 16);
        size_t gb = (size_t)r * Kpad + kt * 16 + q * 8;
        cp16(so, Bh + gb);
        cp16(so + TILE_B, Bl + gb);
        asm volatile("cp.async.commit_group;");
    };

    {
        float4 a0, a1;
        ldgA(0, a0, a1);
        ldgA(1, hv0, hv1);
        cpB(0);
        cpB(1);
        stsA(0, a0, a1);
    }

    const int lane = tid & 31, w = tid >> 5;
    const int wm = w >> 2, wn = w & 3;
    const int lr = lane >> 2, lc = lane & 3;
    const int mat = lane >> 3, r8 = lane & 7;

    float acc[4][4][4];
    #pragma unroll
    for (int a = 0; a < 4; a++)
        #pragma unroll
        for (int b = 0; b < 4; b++)
            #pragma unroll
            for (int d = 0; d < 4; d++) acc[a][b][d] = 0.f;

    for (int kt = 0; kt < KT; ++kt) {
        if (kt < KT - 1) asm volatile("cp.async.wait_group 1;");
        else             asm volatile("cp.async.wait_group 0;");
        __syncthreads();

        if (kt + 1 < KT) stsA((kt + 1) & 1, hv0, hv1);
        if (kt + 2 < KT) ldgA(kt + 2, nv0, nv1);

        uint32_t base = sb + (uint32_t)(kt & 1) * STAGE_B;

        uint32_t bh[2][4], bl[2][4];
        #pragma unroll
        for (int p = 0; p < 2; p++) {
            int brow = wn * 32 + p * 16 + r8 + (mat >> 1) * 8;
            uint32_t addr = base + 2u * TILE_B + (uint32_t)(brow * 48 + ((mat & 1) * 8) * 2);
            ldsm4(bh[p][0], bh[p][1], bh[p][2], bh[p][3], addr);
            ldsm4(bl[p][0], bl[p][1], bl[p][2], bl[p][3], addr + TILE_B);
        }
        #pragma unroll
        for (int mf = 0; mf < 4; ++mf) {
            int arow = wm * 64 + mf * 16 + r8 + (mat & 1) * 8;
            uint32_t aaddr = base + (uint32_t)(arow * 48 + ((mat >> 1) * 8) * 2);
            uint32_t ahr[4], alr[4];
            ldsm4(ahr[0], ahr[1], ahr[2], ahr[3], aaddr);
            ldsm4(alr[0], alr[1], alr[2], alr[3], aaddr + TILE_B);
            #pragma unroll
            for (int nf = 0; nf < 4; ++nf) {
                const uint32_t* bhp = &bh[nf >> 1][(nf & 1) * 2];
                const uint32_t* blp = &bl[nf >> 1][(nf & 1) * 2];
                mma16816(acc[mf][nf], ahr, bhp);
                mma16816(acc[mf][nf], alr, bhp);
                mma16816(acc[mf][nf], ahr, blp);
            }
        }
        __syncthreads();
        if (kt + 2 < KT) {
            cpB(kt + 2);
            hv0 = nv0; hv1 = nv1;
        }
    }

    const bool nb = (nbf != 0) && (bx == 1);   // neighbor half -> fp16 gather array
    #pragma unroll
    for (int mf = 0; mf < 4; ++mf) {
        #pragma unroll
        for (int nf = 0; nf < 4; ++nf) {
            int r = row0 + wm * 64 + mf * 16 + lr;
            int cc = bx * 128 + wn * 32 + nf * 8 + lc * 2;
            if (nb) {
                int cn = cc - 128;
                if (r < M)
                    *reinterpret_cast<__half2*>(g_hnb + (size_t)r * HH + cn) =
                        __floats2half2_rn(acc[mf][nf][0], acc[mf][nf][1]);
                if (r + 8 < M)
                    *reinterpret_cast<__half2*>(g_hnb + (size_t)(r + 8) * HH + cn) =
                        __floats2half2_rn(acc[mf][nf][2], acc[mf][nf][3]);
            } else {
                if (r < M)
                    *reinterpret_cast<float2*>(C + (size_t)r * NCs + cc) =
                        make_float2(acc[mf][nf][0], acc[mf][nf][1]);
                if (r + 8 < M)
                    *reinterpret_cast<float2*>(C + (size_t)(r + 8) * NCs + cc) =
                        make_float2(acc[mf][nf][2], acc[mf][nf][3]);
            }
        }
    }
}

// ---------------- fused CSR gather(fp16) + bias + BN stats (warp-per-node) -----
#define AGG_NPW 16
__global__ void __launch_bounds__(256) k_aggcomb(float* __restrict__ hc,
                                                 const float* __restrict__ bias) {
    __shared__ float sst[256];
    const int tid = threadIdx.x;
    const int lane = tid & 31;
    const int gw = blockIdx.x * 8 + (tid >> 5);
    const int c4 = lane * 4;
    const int n0 = gw * AGG_NPW;
    if (tid < 256) sst[tid] = 0.f;
    __syncthreads();

    if (n0 < NN) {
        const int n1 = min(n0 + AGG_NPW, NN);
        float4 bb = *reinterpret_cast<const float4*>(bias + c4);
        float s0 = 0.f, s1 = 0.f, s2 = 0.f, s3 = 0.f;
        float q0 = 0.f, q1 = 0.f, q2 = 0.f, q3 = 0.f;

        for (int node = n0; node < n1; node++) {
            int p = g_rowptr[node];
            const int e = g_rowptr[node + 1];
            float4 acc = make_float4(0.f, 0.f, 0.f, 0.f);
            for (; p + 3 < e; p += 4) {
                int i0 = __ldg(&g_colidx[p]);
                int i1 = __ldg(&g_colidx[p + 1]);
                int i2 = __ldg(&g_colidx[p + 2]);
                int i3 = __ldg(&g_colidx[p + 3]);
                float4 v0 = ld_hf4(g_hnb + (size_t)i0 * HH + c4);
                float4 v1 = ld_hf4(g_hnb + (size_t)i1 * HH + c4);
                float4 v2 = ld_hf4(g_hnb + (size_t)i2 * HH + c4);
                float4 v3 = ld_hf4(g_hnb + (size_t)i3 * HH + c4);
                acc.x += (v0.x + v1.x) + (v2.x + v3.x);
                acc.y += (v0.y + v1.y) + (v2.y + v3.y);
                acc.z += (v0.z + v1.z) + (v2.z + v3.z);
                acc.w += (v0.w + v1.w) + (v2.w + v3.w);
            }
            for (; p < e; p++) {
                int i0 = __ldg(&g_colidx[p]);
                float4 v0 = ld_hf4(g_hnb + (size_t)i0 * HH + c4);
                acc.x += v0.x; acc.y += v0.y; acc.z += v0.z; acc.w += v0.w;
            }
            float inv = 1.f / g_denom[node];
            float4 self = *reinterpret_cast<const float4*>(hc + (size_t)node * 256 + c4);
            float4 v;
            v.x = self.x + bb.x + acc.x * inv;
            v.y = self.y + bb.y + acc.y * inv;
            v.z = self.z + bb.z + acc.z * inv;
            v.w = self.w + bb.w + acc.w * inv;
            *reinterpret_cast<float4*>(hc + (size_t)node * 256 + c4) = v;
            s0 += v.x; s1 += v.y; s2 += v.z; s3 += v.w;
            q0 += v.x * v.x; q1 += v.y * v.y; q2 += v.z * v.z; q3 += v.w * v.w;
        }
        atomicAdd(&sst[c4 + 0], s0);
        atomicAdd(&sst[c4 + 1], s1);
        atomicAdd(&sst[c4 + 2], s2);
        atomicAdd(&sst[c4 + 3], s3);
        atomicAdd(&sst[HH + c4 + 0], q0);
        atomicAdd(&sst[HH + c4 + 1], q1);
        atomicAdd(&sst[HH + c4 + 2], q2);
        atomicAdd(&sst[HH + c4 + 3], q3);
    }
    __syncthreads();
    if (tid < 256) atomicAdd(&g_stats[tid], sst[tid]);
}

// head: pre stride 128, active cols = 64 (blockDim.x)
__global__ void k_combineH(float* __restrict__ pre, const float* __restrict__ bias,
                           int rows) {
    int c = threadIdx.x;                 // 64 threads
    int r0 = blockIdx.x * rows;
    int r1 = min(r0 + rows, NN);
    float bb = bias[c];
    float s = 0.f, s2 = 0.f;
    for (int r = r0; r < r1; r++) {
        float v = pre[(size_t)r * 128 + c] + bb;
        pre[(size_t)r * 128 + c] = v;
        s += v;
        s2 += v * v;
    }
    atomicAdd(&g_stats[c], s);
    atomicAdd(&g_stats[64 + c], s2);
}

// compute BN scale/offset, then self-zero stats for the next accumulation
__global__ void k_finalize(const float* __restrict__ gamma, const float* __restrict__ beta, int M) {
    int c = threadIdx.x;
    int Hc = blockDim.x;
    float inv_m = 1.f / (float)M;
    float mean = g_stats[c] * inv_m;
    float var = g_stats[Hc + c] * inv_m - mean * mean;
    float a = gamma[c] * rsqrtf(var + EPSV);
    g_ab[c] = a;
    g_ab[Hc + c] = beta[c] - mean * a;
    g_stats[c] = 0.f;
    g_stats[Hc + c] = 0.f;
}

// BN + (residual) + ReLU -> h
__global__ void k_norm(const float* __restrict__ pre, float* __restrict__ h,
                       const float* __restrict__ resid) {
    int i = blockIdx.x * blockDim.x + threadIdx.x;
    if (i >= NN * 32) return;
    int r = i >> 5, q = i & 31;
    float4 p = *reinterpret_cast<const float4*>(pre + (size_t)r * 256 + q * 4);
    float4 a = *reinterpret_cast<const float4*>(g_ab + q * 4);
    float4 b = *reinterpret_cast<const float4*>(g_ab + HH + q * 4);
    float4 v;
    v.x = fmaf(p.x, a.x, b.x); v.y = fmaf(p.y, a.y, b.y);
    v.z = fmaf(p.z, a.z, b.z); v.w = fmaf(p.w, a.w, b.w);
    if (resid) {
        float4 rr = *reinterpret_cast<const float4*>(resid + (size_t)r * HH + q * 4);
        v.x += rr.x; v.y += rr.y; v.z += rr.z; v.w += rr.w;
    }
    v.x = fmaxf(v.x, 0.f); v.y = fmaxf(v.y, 0.f);
    v.z = fmaxf(v.z, 0.f); v.w = fmaxf(v.w, 0.f);
    *reinterpret_cast<float4*>(h + (size_t)r * HH + q * 4) = v;
}

// final head: BN -> relu -> @W2 + b2, one warp per node (zpre stride 128)
__global__ void k_output(const float* __restrict__ zpre, const float* __restrict__ W2,
                         const float* __restrict__ b2, float* __restrict__ out) {
    int gtid = blockIdx.x * blockDim.x + threadIdx.x;
    int node = gtid >> 5;
    int lane = gtid & 31;
    if (node >= NN) return;
    float acc = 0.f;
    #pragma unroll
    for (int j = lane; j < 64; j += 32) {
        float v = fmaf(zpre[(size_t)node * 128 + j], g_ab[j], g_ab[64 + j]);
        v = fmaxf(v, 0.f);
        acc += v * W2[j];
    }
    #pragma unroll
    for (int o = 16; o; o >>= 1) acc += __shfl_xor_sync(0xFFFFFFFFu, acc, o);
    if (lane == 0) out[node] = acc + b2[0];
}

// ---------------- host orchestration ------------------------------------------
extern "C" void kernel_launch(void* const* d_in, const int* in_sizes, int n_in,
                              void* d_out, int out_size) {
    const float* inputs   = (const float*)d_in[0];
    const int*   graph    = (const int*)  d_in[1];
    const float* Wself0   = (const float*)d_in[2];
    const float* Wneigh0  = (const float*)d_in[3];
    const float* b0       = (const float*)d_in[4];
    const float* Wself    = (const float*)d_in[5];
    const float* Wneigh   = (const float*)d_in[6];
    const float* bvec     = (const float*)d_in[7];
    const float* bn_gamma = (const float*)d_in[8];
    const float* bn_beta  = (const float*)d_in[9];
    const float* W1       = (const float*)d_in[10];
    const float* b1       = (const float*)d_in[11];
    const float* bng1     = (const float*)d_in[12];
    const float* bnb1     = (const float*)d_in[13];
    const float* W2       = (const float*)d_in[14];
    const float* b2       = (const float*)d_in[15];
    float* out = (float*)d_out;

    float *h, *hc, *z;
    __nv_bfloat16 *B0h, *B0l, *BLh, *BLl, *BHh, *BHl;
    cudaGetSymbolAddress((void**)&h,   g_h);
    cudaGetSymbolAddress((void**)&hc,  g_hc);
    cudaGetSymbolAddress((void**)&z,   g_z);
    cudaGetSymbolAddress((void**)&B0h, g_B0h);
    cudaGetSymbolAddress((void**)&B0l, g_B0l);
    cudaGetSymbolAddress((void**)&BLh, g_BLh);
    cudaGetSymbolAddress((void**)&BLl, g_BLl);
    cudaGetSymbolAddress((void**)&BHh, g_BHh);
    cudaGetSymbolAddress((void**)&BHl, g_BHl);

    const int TB = 256;
    const int gN = (NN + TB - 1) / TB;
    const int gE = (EE + TB - 1) / TB;
    const dim3 gemmGrid(2, (NN + 127) / 128);
    const dim3 headGrid(1, (NN + 127) / 128);
    const int gNorm = (NN * 32 + TB - 1) / TB;
    const int gAgg = (NN + 8 * AGG_NPW - 1) / (8 * AGG_NPW);

    cudaStream_t s2 = 0;
    cudaEvent_t evFork = 0, evJoin = 0;
    bool forked = (cudaStreamCreateWithFlags(&s2, cudaStreamNonBlocking) == cudaSuccess);
    if (forked) {
        cudaEventCreateWithFlags(&evFork, cudaEventDisableTiming);
        cudaEventCreateWithFlags(&evJoin, cudaEventDisableTiming);
    }
    cudaStream_t sc = forked ? s2 : 0;

    // ---- main stream: layer-0 weight conversion ----
    k_convW0<<<(256 * K0P + TB - 1) / TB, TB>>>(Wself0, Wneigh0);

    if (forked) {
        cudaEventRecord(evFork, 0);
        cudaStreamWaitEvent(s2, evFork, 0);
    }

    // ---- CSR branch (overlaps layer-0 GEMM) ----
    k_convWL<<<(3 * 256 * HH + TB - 1) / TB, TB, 0, sc>>>(Wself, Wneigh);
    k_convW1<<<(128 * HH + TB - 1) / TB, TB, 0, sc>>>(W1);
    k_zero_deg<<<gN, TB, 0, sc>>>();
    k_count<<<gE, TB, 0, sc>>>(graph);
    k_scan1<<<(NN + 1023) / 1024, 1024, 0, sc>>>();
    k_scan2<<<1, 32, 0, sc>>>();
    k_scan3<<<gN, TB, 0, sc>>>();
    k_fill<<<gE, TB, 0, sc>>>(graph);
    if (forked) cudaEventRecord(evJoin, s2);

    // ---- layer 0 GEMM (concurrent with CSR branch) ----
    gemm_split<<<gemmGrid, 256>>>(inputs, FIN, K0P, B0h, B0l, hc, NN, 256, 1);

    if (forked) cudaStreamWaitEvent(0, evJoin, 0);

    // ---- layer 0 epilogue ----
    k_aggcomb<<<gAgg, 256>>>(hc, b0);
    k_finalize<<<1, HH>>>(bn_gamma, bn_beta, NN);
    k_norm<<<gNorm, TB>>>(hc, h, nullptr);

    // ---- layers 1..3 ----
    for (int l = 0; l < 3; l++) {
        gemm_split<<<gemmGrid, 256>>>(h, HH, HH,
                                      BLh + (size_t)l * 256 * HH,
                                      BLl + (size_t)l * 256 * HH,
                                      hc, NN, 256, 1);
        k_aggcomb<<<gAgg, 256>>>(hc, bvec + (size_t)l * HH);
        k_finalize<<<1, HH>>>(bn_gamma + (size_t)(l + 1) * HH, bn_beta + (size_t)(l + 1) * HH, NN);
        k_norm<<<gNorm, TB>>>(hc, h, h);
    }

    // ---- head (tensor GEMM on padded W1, z stride 128) ----
    gemm_split<<<headGrid, 256>>>(h, HH, HH, BHh, BHl, z, NN, 128, 0);
    k_combineH<<<(NN + 127) / 128, 64>>>(z, b1, 128);
    k_finalize<<<1, 64>>>(bng1, bnb1, NN);
    k_output<<<(NN * 32 + TB - 1) / TB, TB>>>(z, W2, b2, out);

    (void)in_sizes; (void)n_in; (void)out_size;
}

// round 16
// speedup vs baseline: 1.1993x; 1.0391x over previous
#include <cuda_runtime.h>
#include <cuda_bf16.h>
#include <cuda_fp16.h>
#include <math.h>
#include <stdint.h>

#define NN   100000
#define EE   1600000
#define FIN  700
#define K0P  704
#define HH   128
#define EPSV 1e-5f

// ---------------- scratch (static device globals; zero-init, no runtime alloc) ----
__device__ __half g_h [(size_t)NN * HH];         // activations, fp16
__device__ float g_hc [(size_t)NN * 256];        // [self(128) | unused]
__device__ __half g_hnb[(size_t)NN * HH];        // neigh half as fp16 (gather source)
__device__ float g_z  [(size_t)NN * 128];        // head pre-activations (stride 128)
__device__ float g_denom[NN];
__device__ int   g_deg[NN];
__device__ int   g_rowptr[NN + 1];
__device__ int   g_colidx[EE];
__device__ int   g_bsums[128];
__device__ __align__(16) float g_stats[256];
__device__ __align__(16) float g_ab[256];

// bf16 split weights (A operands are split in-GEMM)
__device__ __nv_bfloat16 g_B0h[256 * K0P];
__device__ __nv_bfloat16 g_B0l[256 * K0P];
__device__ __nv_bfloat16 g_BLh[3 * 256 * HH];
__device__ __nv_bfloat16 g_BLl[3 * 256 * HH];
__device__ __nv_bfloat16 g_BHh[128 * HH];        // head W1 padded to 128 cols
__device__ __nv_bfloat16 g_BHl[128 * HH];

// ---------------- helpers ------------------------------------------------------
__device__ __forceinline__ void split_bf16(float x, __nv_bfloat16& h, __nv_bfloat16& l) {
    h = __float2bfloat16(x);
    l = __float2bfloat16(x - __bfloat162float(h));
}
__device__ __forceinline__ uint32_t pkbf2(__nv_bfloat16 a, __nv_bfloat16 b) {
    __nv_bfloat162 t = __halves2bfloat162(a, b);
    return *reinterpret_cast<uint32_t*>(&t);
}
__device__ __forceinline__ float4 ld_hf4(const __half* p) {
    uint2 raw = *reinterpret_cast<const uint2*>(p);
    __half2 a = *reinterpret_cast<__half2*>(&raw.x);
    __half2 b = *reinterpret_cast<__half2*>(&raw.y);
    float2 fa = __half22float2(a), fb = __half22float2(b);
    return make_float4(fa.x, fa.y, fb.x, fb.y);
}
__device__ __forceinline__ void cp16(uint32_t s, const void* g) {
    asm volatile("cp.async.cg.shared.global [%0], [%1], 16;" :: "r"(s), "l"(g));
}
__device__ __forceinline__ void ldsm4(uint32_t& r0, uint32_t& r1, uint32_t& r2, uint32_t& r3, uint32_t a) {
    asm volatile("ldmatrix.sync.aligned.m8n8.x4.shared.b16 {%0,%1,%2,%3}, [%4];"
                 : "=r"(r0), "=r"(r1), "=r"(r2), "=r"(r3) : "r"(a));
}
__device__ __forceinline__ void mma16816(float* c, const uint32_t* a, const uint32_t* b) {
    asm volatile("mma.sync.aligned.m16n8k16.row.col.f32.bf16.bf16.f32 "
                 "{%0,%1,%2,%3}, {%4,%5,%6,%7}, {%8,%9}, {%0,%1,%2,%3};"
                 : "+f"(c[0]), "+f"(c[1]), "+f"(c[2]), "+f"(c[3])
                 : "r"(a[0]), "r"(a[1]), "r"(a[2]), "r"(a[3]), "r"(b[0]), "r"(b[1]));
}

// ---------------- CSR construction --------------------------------------------
__global__ void k_zero_deg() {
    int i = blockIdx.x * blockDim.x + threadIdx.x;
    if (i < NN) g_deg[i] = 0;
}
__global__ void k_count(const int* __restrict__ graph) {
    int e = blockIdx.x * blockDim.x + threadIdx.x;
    if (e < EE) atomicAdd(&g_deg[graph[2 * e + 1]], 1);
}
__global__ void k_scan1() {
    __shared__ int s[1024];
    int tid = threadIdx.x;
    int i = blockIdx.x * 1024 + tid;
    int v = (i < NN) ? g_deg[i] : 0;
    s[tid] = v;
    __syncthreads();
    #pragma unroll
    for (int off = 1; off < 1024; off <<= 1) {
        int t = (tid >= off) ? s[tid - off] : 0;
        __syncthreads();
        s[tid] += t;
        __syncthreads();
    }
    if (i < NN) g_rowptr[i + 1] = s[tid];
    if (tid == 1023) g_bsums[blockIdx.x] = s[1023];
}
__global__ void k_scan2() {
    if (threadIdx.x == 0) {
        const int nb = (NN + 1023) / 1024;
        int acc = 0;
        for (int i = 0; i < nb; i++) { int t = g_bsums[i]; g_bsums[i] = acc; acc += t; }
    }
}
__global__ void k_scan3() {
    int i = blockIdx.x * blockDim.x + threadIdx.x;
    if (i >= NN) return;
    g_rowptr[i + 1] += g_bsums[i >> 10];
    if (i == 0) g_rowptr[0] = 0;
    int d = g_deg[i];
    g_denom[i] = (float)((d > 1) ? d : 1);
    g_deg[i] = 0;
}
__global__ void k_fill(const int* __restrict__ graph) {
    int e = blockIdx.x * blockDim.x + threadIdx.x;
    if (e >= EE) return;
    int src = graph[2 * e + 0];
    int dst = graph[2 * e + 1];
    int pos = g_rowptr[dst] + atomicAdd(&g_deg[dst], 1);
    g_colidx[pos] = src;
}

// ---------------- weight conversion --------------------------------------------
__global__ void k_convW0(const float* __restrict__ Ws, const float* __restrict__ Wn) {
    int idx = blockIdx.x * blockDim.x + threadIdx.x;
    if (idx >= 256 * K0P) return;
    int n = idx / K0P, k = idx % K0P;
    float v = 0.f;
    if (k < FIN) v = (n < HH) ? Ws[(size_t)k * HH + n] : Wn[(size_t)k * HH + (n - HH)];
    split_bf16(v, g_B0h[idx], g_B0l[idx]);
}
__global__ void k_convWL(const float* __restrict__ Ws, const float* __restrict__ Wn) {
    int idx = blockIdx.x * blockDim.x + threadIdx.x;
    if (idx >= 3 * 256 * HH) return;
    int l = idx / (256 * HH);
    int rem = idx % (256 * HH);
    int n = rem / HH, k = rem % HH;
    float v = (n < HH) ? Ws[(size_t)l * HH * HH + k * HH + n]
                       : Wn[(size_t)l * HH * HH + k * HH + (n - HH)];
    split_bf16(v, g_BLh[idx], g_BLl[idx]);
}
__global__ void k_convW1(const float* __restrict__ W1) {
    int idx = blockIdx.x * blockDim.x + threadIdx.x;
    if (idx >= 128 * HH) return;
    int n = idx / HH, k = idx % HH;
    float v = (n < 64) ? W1[(size_t)k * 64 + n] : 0.f;
    split_bf16(v, g_BHh[idx], g_BHl[idx]);
}

// ---------------- split-precision tensor GEMM ----------------------------------
// R11 inner loop (frozen). A is fp32 (a16=0) or fp16 (a16=1; split is exact).
// When nbf!=0 and bx==1, epilogue writes neighbor half as fp16 into g_hnb.
#define TILE_B 6144
#define STAGE_B 24576
__global__ void __launch_bounds__(256) gemm_split(
    const void* __restrict__ Av, int K, int Kpad,
    const __nv_bfloat16* __restrict__ Bh0, const __nv_bfloat16* __restrict__ Bl0,
    float* __restrict__ C, int M, int NCs, int nbf, int a16)
{
    __shared__ __align__(16) char smem[49152];
    const uint32_t sb = (uint32_t)__cvta_generic_to_shared(smem);
    const int tid = threadIdx.x;
    const int bx = blockIdx.x, by = blockIdx.y;
    const int row0 = by * 128;
    const __nv_bfloat16* Bh = Bh0 + (size_t)bx * 128 * Kpad;
    const __nv_bfloat16* Bl = Bl0 + (size_t)bx * 128 * Kpad;
    const int KT = Kpad >> 4;

    const int ar = tid >> 1, aq = tid & 1;
    const int agr = row0 + ar;
    const char* Arow = (const char*)Av + (size_t)agr * K * (a16 ? 2 : 4);

    float4 hv0, hv1;
    float4 nv0, nv1;

    auto ldgA = [&](int kt, float4& v0, float4& v1) {
        v0 = make_float4(0.f, 0.f, 0.f, 0.f);
        v1 = v0;
        int kb = kt * 16 + aq * 8;
        if (agr < M) {
            if (a16) {
                if (kb < K) {   // fp16 rows: K multiple of 16, one 16B read = 8 halfs
                    uint4 r = *reinterpret_cast<const uint4*>(Arow + (size_t)kb * 2);
                    __half2* hp = reinterpret_cast<__half2*>(&r);
                    float2 f0 = __half22float2(hp[0]), f1 = __half22float2(hp[1]);
                    float2 f2 = __half22float2(hp[2]), f3 = __half22float2(hp[3]);
                    v0 = make_float4(f0.x, f0.y, f1.x, f1.y);
                    v1 = make_float4(f2.x, f2.y, f3.x, f3.y);
                }
            } else {
                if (kb + 3 < K) v0 = *reinterpret_cast<const float4*>(Arow + (size_t)kb * 4);
                if (kb + 7 < K) v1 = *reinterpret_cast<const float4*>(Arow + (size_t)(kb + 4) * 4);
            }
        }
    };
    auto stsA = [&](int stage, float4 v0, float4 v1) {
        float f[8] = {v0.x, v0.y, v0.z, v0.w, v1.x, v1.y, v1.z, v1.w};
        __nv_bfloat16 hh[8], ll[8];
        #pragma unroll
        for (int i = 0; i < 8; i++) split_bf16(f[i], hh[i], ll[i]);
        uint4 hvv, lvv;
        hvv.x = pkbf2(hh[0], hh[1]); hvv.y = pkbf2(hh[2], hh[3]);
        hvv.z = pkbf2(hh[4], hh[5]); hvv.w = pkbf2(hh[6], hh[7]);
        lvv.x = pkbf2(ll[0], ll[1]); lvv.y = pkbf2(ll[2], ll[3]);
        lvv.z = pkbf2(ll[4], ll[5]); lvv.w = pkbf2(ll[6], ll[7]);
        char* dst = smem + stage * STAGE_B + ar * 48 + aq * 16;
        *reinterpret_cast<uint4*>(dst) = hvv;
        *reinterpret_cast<uint4*>(dst + TILE_B) = lvv;
    };
    auto cpB = [&](int kt) {
        uint32_t base = sb + (uint32_t)(kt & 1) * STAGE_B + 2u * TILE_B;
        int r = tid >> 1, q = tid & 1;
        uint32_t so = base + (uint32_t)(r * 48 + q * 16);
        size_t gb = (size_t)r * Kpad + kt * 16 + q * 8;
        cp16(so, Bh + gb);
        cp16(so + TILE_B, Bl + gb);
        asm volatile("cp.async.commit_group;");
    };

    {
        float4 a0, a1;
        ldgA(0, a0, a1);
        ldgA(1, hv0, hv1);
        cpB(0);
        cpB(1);
        stsA(0, a0, a1);
    }

    const int lane = tid & 31, w = tid >> 5;
    const int wm = w >> 2, wn = w & 3;
    const int lr = lane >> 2, lc = lane & 3;
    const int mat = lane >> 3, r8 = lane & 7;

    float acc[4][4][4];
    #pragma unroll
    for (int a = 0; a < 4; a++)
        #pragma unroll
        for (int b = 0; b < 4; b++)
            #pragma unroll
            for (int d = 0; d < 4; d++) acc[a][b][d] = 0.f;

    for (int kt = 0; kt < KT; ++kt) {
        if (kt < KT - 1) asm volatile("cp.async.wait_group 1;");
        else             asm volatile("cp.async.wait_group 0;");
        __syncthreads();

        if (kt + 1 < KT) stsA((kt + 1) & 1, hv0, hv1);
        if (kt + 2 < KT) ldgA(kt + 2, nv0, nv1);

        uint32_t base = sb + (uint32_t)(kt & 1) * STAGE_B;

        uint32_t bh[2][4], bl[2][4];
        #pragma unroll
        for (int p = 0; p < 2; p++) {
            int brow = wn * 32 + p * 16 + r8 + (mat >> 1) * 8;
            uint32_t addr = base + 2u * TILE_B + (uint32_t)(brow * 48 + ((mat & 1) * 8) * 2);
            ldsm4(bh[p][0], bh[p][1], bh[p][2], bh[p][3], addr);
            ldsm4(bl[p][0], bl[p][1], bl[p][2], bl[p][3], addr + TILE_B);
        }
        #pragma unroll
        for (int mf = 0; mf < 4; ++mf) {
            int arow = wm * 64 + mf * 16 + r8 + (mat & 1) * 8;
            uint32_t aaddr = base + (uint32_t)(arow * 48 + ((mat >> 1) * 8) * 2);
            uint32_t ahr[4], alr[4];
            ldsm4(ahr[0], ahr[1], ahr[2], ahr[3], aaddr);
            ldsm4(alr[0], alr[1], alr[2], alr[3], aaddr + TILE_B);
            #pragma unroll
            for (int nf = 0; nf < 4; ++nf) {
                const uint32_t* bhp = &bh[nf >> 1][(nf & 1) * 2];
                const uint32_t* blp = &bl[nf >> 1][(nf & 1) * 2];
                mma16816(acc[mf][nf], ahr, bhp);
                mma16816(acc[mf][nf], alr, bhp);
                mma16816(acc[mf][nf], ahr, blp);
            }
        }
        __syncthreads();
        if (kt + 2 < KT) {
            cpB(kt + 2);
            hv0 = nv0; hv1 = nv1;
        }
    }

    const bool nb = (nbf != 0) && (bx == 1);   // neighbor half -> fp16 gather array
    #pragma unroll
    for (int mf = 0; mf < 4; ++mf) {
        #pragma unroll
        for (int nf = 0; nf < 4; ++nf) {
            int r = row0 + wm * 64 + mf * 16 + lr;
            int cc = bx * 128 + wn * 32 + nf * 8 + lc * 2;
            if (nb) {
                int cn = cc - 128;
                if (r < M)
                    *reinterpret_cast<__half2*>(g_hnb + (size_t)r * HH + cn) =
                        __floats2half2_rn(acc[mf][nf][0], acc[mf][nf][1]);
                if (r + 8 < M)
                    *reinterpret_cast<__half2*>(g_hnb + (size_t)(r + 8) * HH + cn) =
                        __floats2half2_rn(acc[mf][nf][2], acc[mf][nf][3]);
            } else {
                if (r < M)
                    *reinterpret_cast<float2*>(C + (size_t)r * NCs + cc) =
                        make_float2(acc[mf][nf][0], acc[mf][nf][1]);
                if (r + 8 < M)
                    *reinterpret_cast<float2*>(C + (size_t)(r + 8) * NCs + cc) =
                        make_float2(acc[mf][nf][2], acc[mf][nf][3]);
            }
        }
    }
}

// ---------------- fused CSR gather(fp16) + bias + BN stats (warp-per-node) -----
#define AGG_NPW 16
__global__ void __launch_bounds__(256) k_aggcomb(float* __restrict__ hc,
                                                 const float* __restrict__ bias) {
    __shared__ float sst[256];
    const int tid = threadIdx.x;
    const int lane = tid & 31;
    const int gw = blockIdx.x * 8 + (tid >> 5);
    const int c4 = lane * 4;
    const int n0 = gw * AGG_NPW;
    if (tid < 256) sst[tid] = 0.f;
    __syncthreads();

    if (n0 < NN) {
        const int n1 = min(n0 + AGG_NPW, NN);
        float4 bb = *reinterpret_cast<const float4*>(bias + c4);
        float s0 = 0.f, s1 = 0.f, s2 = 0.f, s3 = 0.f;
        float q0 = 0.f, q1 = 0.f, q2 = 0.f, q3 = 0.f;

        for (int node = n0; node < n1; node++) {
            int p = g_rowptr[node];
            const int e = g_rowptr[node + 1];
            float4 acc = make_float4(0.f, 0.f, 0.f, 0.f);
            for (; p + 3 < e; p += 4) {
                int i0 = __ldg(&g_colidx[p]);
                int i1 = __ldg(&g_colidx[p + 1]);
                int i2 = __ldg(&g_colidx[p + 2]);
                int i3 = __ldg(&g_colidx[p + 3]);
                float4 v0 = ld_hf4(g_hnb + (size_t)i0 * HH + c4);
                float4 v1 = ld_hf4(g_hnb + (size_t)i1 * HH + c4);
                float4 v2 = ld_hf4(g_hnb + (size_t)i2 * HH + c4);
                float4 v3 = ld_hf4(g_hnb + (size_t)i3 * HH + c4);
                acc.x += (v0.x + v1.x) + (v2.x + v3.x);
                acc.y += (v0.y + v1.y) + (v2.y + v3.y);
                acc.z += (v0.z + v1.z) + (v2.z + v3.z);
                acc.w += (v0.w + v1.w) + (v2.w + v3.w);
            }
            for (; p < e; p++) {
                int i0 = __ldg(&g_colidx[p]);
                float4 v0 = ld_hf4(g_hnb + (size_t)i0 * HH + c4);
                acc.x += v0.x; acc.y += v0.y; acc.z += v0.z; acc.w += v0.w;
            }
            float inv = 1.f / g_denom[node];
            float4 self = *reinterpret_cast<const float4*>(hc + (size_t)node * 256 + c4);
            float4 v;
            v.x = self.x + bb.x + acc.x * inv;
            v.y = self.y + bb.y + acc.y * inv;
            v.z = self.z + bb.z + acc.z * inv;
            v.w = self.w + bb.w + acc.w * inv;
            *reinterpret_cast<float4*>(hc + (size_t)node * 256 + c4) = v;
            s0 += v.x; s1 += v.y; s2 += v.z; s3 += v.w;
            q0 += v.x * v.x; q1 += v.y * v.y; q2 += v.z * v.z; q3 += v.w * v.w;
        }
        atomicAdd(&sst[c4 + 0], s0);
        atomicAdd(&sst[c4 + 1], s1);
        atomicAdd(&sst[c4 + 2], s2);
        atomicAdd(&sst[c4 + 3], s3);
        atomicAdd(&sst[HH + c4 + 0], q0);
        atomicAdd(&sst[HH + c4 + 1], q1);
        atomicAdd(&sst[HH + c4 + 2], q2);
        atomicAdd(&sst[HH + c4 + 3], q3);
    }
    __syncthreads();
    if (tid < 256) atomicAdd(&g_stats[tid], sst[tid]);
}

// head: pre stride 128, active cols = 64 (blockDim.x)
__global__ void k_combineH(float* __restrict__ pre, const float* __restrict__ bias,
                           int rows) {
    int c = threadIdx.x;                 // 64 threads
    int r0 = blockIdx.x * rows;
    int r1 = min(r0 + rows, NN);
    float bb = bias[c];
    float s = 0.f, s2 = 0.f;
    for (int r = r0; r < r1; r++) {
        float v = pre[(size_t)r * 128 + c] + bb;
        pre[(size_t)r * 128 + c] = v;
        s += v;
        s2 += v * v;
    }
    atomicAdd(&g_stats[c], s);
    atomicAdd(&g_stats[64 + c], s2);
}

// compute BN scale/offset, then self-zero stats for the next accumulation
__global__ void k_finalize(const float* __restrict__ gamma, const float* __restrict__ beta, int M) {
    int c = threadIdx.x;
    int Hc = blockDim.x;
    float inv_m = 1.f / (float)M;
    float mean = g_stats[c] * inv_m;
    float var = g_stats[Hc + c] * inv_m - mean * mean;
    float a = gamma[c] * rsqrtf(var + EPSV);
    g_ab[c] = a;
    g_ab[Hc + c] = beta[c] - mean * a;
    g_stats[c] = 0.f;
    g_stats[Hc + c] = 0.f;
}

// BN + (residual, fp16) + ReLU -> h (fp16)
__global__ void k_norm(const float* __restrict__ pre, __half* __restrict__ h,
                       const __half* __restrict__ resid) {
    int i = blockIdx.x * blockDim.x + threadIdx.x;
    if (i >= NN * 32) return;
    int r = i >> 5, q = i & 31;
    float4 p = *reinterpret_cast<const float4*>(pre + (size_t)r * 256 + q * 4);
    float4 a = *reinterpret_cast<const float4*>(g_ab + q * 4);
    float4 b = *reinterpret_cast<const float4*>(g_ab + HH + q * 4);
    float4 v;
    v.x = fmaf(p.x, a.x, b.x); v.y = fmaf(p.y, a.y, b.y);
    v.z = fmaf(p.z, a.z, b.z); v.w = fmaf(p.w, a.w, b.w);
    if (resid) {
        float4 rr = ld_hf4(resid + (size_t)r * HH + q * 4);
        v.x += rr.x; v.y += rr.y; v.z += rr.z; v.w += rr.w;
    }
    v.x = fmaxf(v.x, 0.f); v.y = fmaxf(v.y, 0.f);
    v.z = fmaxf(v.z, 0.f); v.w = fmaxf(v.w, 0.f);
    __half2 o0 = __floats2half2_rn(v.x, v.y);
    __half2 o1 = __floats2half2_rn(v.z, v.w);
    uint2 ov;
    ov.x = *reinterpret_cast<uint32_t*>(&o0);
    ov.y = *reinterpret_cast<uint32_t*>(&o1);
    *reinterpret_cast<uint2*>(h + (size_t)r * HH + q * 4) = ov;
}

// final head: BN -> relu -> @W2 + b2, one warp per node (zpre stride 128)
__global__ void k_output(const float* __restrict__ zpre, const float* __restrict__ W2,
                         const float* __restrict__ b2, float* __restrict__ out) {
    int gtid = blockIdx.x * blockDim.x + threadIdx.x;
    int node = gtid >> 5;
    int lane = gtid & 31;
    if (node >= NN) return;
    float acc = 0.f;
    #pragma unroll
    for (int j = lane; j < 64; j += 32) {
        float v = fmaf(zpre[(size_t)node * 128 + j], g_ab[j], g_ab[64 + j]);
        v = fmaxf(v, 0.f);
        acc += v * W2[j];
    }
    #pragma unroll
    for (int o = 16; o; o >>= 1) acc += __shfl_xor_sync(0xFFFFFFFFu, acc, o);
    if (lane == 0) out[node] = acc + b2[0];
}

// ---------------- host orchestration ------------------------------------------
extern "C" void kernel_launch(void* const* d_in, const int* in_sizes, int n_in,
                              void* d_out, int out_size) {
    const float* inputs   = (const float*)d_in[0];
    const int*   graph    = (const int*)  d_in[1];
    const float* Wself0   = (const float*)d_in[2];
    const float* Wneigh0  = (const float*)d_in[3];
    const float* b0       = (const float*)d_in[4];
    const float* Wself    = (const float*)d_in[5];
    const float* Wneigh   = (const float*)d_in[6];
    const float* bvec     = (const float*)d_in[7];
    const float* bn_gamma = (const float*)d_in[8];
    const float* bn_beta  = (const float*)d_in[9];
    const float* W1       = (const float*)d_in[10];
    const float* b1       = (const float*)d_in[11];
    const float* bng1     = (const float*)d_in[12];
    const float* bnb1     = (const float*)d_in[13];
    const float* W2       = (const float*)d_in[14];
    const float* b2       = (const float*)d_in[15];
    float* out = (float*)d_out;

    float *hc, *z;
    __half *h;
    __nv_bfloat16 *B0h, *B0l, *BLh, *BLl, *BHh, *BHl;
    cudaGetSymbolAddress((void**)&h,   g_h);
    cudaGetSymbolAddress((void**)&hc,  g_hc);
    cudaGetSymbolAddress((void**)&z,   g_z);
    cudaGetSymbolAddress((void**)&B0h, g_B0h);
    cudaGetSymbolAddress((void**)&B0l, g_B0l);
    cudaGetSymbolAddress((void**)&BLh, g_BLh);
    cudaGetSymbolAddress((void**)&BLl, g_BLl);
    cudaGetSymbolAddress((void**)&BHh, g_BHh);
    cudaGetSymbolAddress((void**)&BHl, g_BHl);

    const int TB = 256;
    const int gN = (NN + TB - 1) / TB;
    const int gE = (EE + TB - 1) / TB;
    const dim3 gemmGrid(2, (NN + 127) / 128);
    const dim3 headGrid(1, (NN + 127) / 128);
    const int gNorm = (NN * 32 + TB - 1) / TB;
    const int gAgg = (NN + 8 * AGG_NPW - 1) / (8 * AGG_NPW);

    cudaStream_t s2 = 0;
    cudaEvent_t evFork = 0, evJoin = 0;
    bool forked = (cudaStreamCreateWithFlags(&s2, cudaStreamNonBlocking) == cudaSuccess);
    if (forked) {
        cudaEventCreateWithFlags(&evFork, cudaEventDisableTiming);
        cudaEventCreateWithFlags(&evJoin, cudaEventDisableTiming);
    }
    cudaStream_t sc = forked ? s2 : 0;

    // ---- main stream: layer-0 weight conversion ----
    k_convW0<<<(256 * K0P + TB - 1) / TB, TB>>>(Wself0, Wneigh0);

    if (forked) {
        cudaEventRecord(evFork, 0);
        cudaStreamWaitEvent(s2, evFork, 0);
    }

    // ---- CSR branch (overlaps layer-0 GEMM) ----
    k_convWL<<<(3 * 256 * HH + TB - 1) / TB, TB, 0, sc>>>(Wself, Wneigh);
    k_convW1<<<(128 * HH + TB - 1) / TB, TB, 0, sc>>>(W1);
    k_zero_deg<<<gN, TB, 0, sc>>>();
    k_count<<<gE, TB, 0, sc>>>(graph);
    k_scan1<<<(NN + 1023) / 1024, 1024, 0, sc>>>();
    k_scan2<<<1, 32, 0, sc>>>();
    k_scan3<<<gN, TB, 0, sc>>>();
    k_fill<<<gE, TB, 0, sc>>>(graph);
    if (forked) cudaEventRecord(evJoin, s2);

    // ---- layer 0 GEMM (fp32 A; concurrent with CSR branch) ----
    gemm_split<<<gemmGrid, 256>>>(inputs, FIN, K0P, B0h, B0l, hc, NN, 256, 1, 0);

    if (forked) cudaStreamWaitEvent(0, evJoin, 0);

    // ---- layer 0 epilogue ----
    k_aggcomb<<<gAgg, 256>>>(hc, b0);
    k_finalize<<<1, HH>>>(bn_gamma, bn_beta, NN);
    k_norm<<<gNorm, TB>>>(hc, h, nullptr);

    // ---- layers 1..3 (fp16 A) ----
    for (int l = 0; l < 3; l++) {
        gemm_split<<<gemmGrid, 256>>>(h, HH, HH,
                                      BLh + (size_t)l * 256 * HH,
                                      BLl + (size_t)l * 256 * HH,
                                      hc, NN, 256, 1, 1);
        k_aggcomb<<<gAgg, 256>>>(hc, bvec + (size_t)l * HH);
        k_finalize<<<1, HH>>>(bn_gamma + (size_t)(l + 1) * HH, bn_beta + (size_t)(l + 1) * HH, NN);
        k_norm<<<gNorm, TB>>>(hc, h, (l < 3) ? h : nullptr);
    }

    // ---- head (tensor GEMM on padded W1, fp16 A, z stride 128) ----
    gemm_split<<<headGrid, 256>>>(h, HH, HH, BHh, BHl, z, NN, 128, 0, 1);
    k_combineH<<<(NN + 127) / 128, 64>>>(z, b1, 128);
    k_finalize<<<1, 64>>>(bng1, bnb1, NN);
    k_output<<<(NN * 32 + TB - 1) / TB, TB>>>(z, W2, b2, out);

    (void)in_sizes; (void)n_in; (void)out_size;
}